// round 1
// baseline (speedup 1.0000x reference)
#include <cuda_runtime.h>
#include <cuda_bf16.h>
#include <math.h>

// ---------------- static problem shapes ----------------
#define BB    8
#define NTOK  16384            // 128*128
#define CC    64
#define HIDD  256
#define NRTOK 256              // (128/8)*(128/8)
#define NPATCH 2048            // BB*NRTOK

// ---------------- scratch (device globals; no allocations) ----------------
__device__ float g_h [(size_t)BB*NTOK*CC];    // ln1 out, later reused as ln2 out
__device__ float g_q [(size_t)BB*NTOK*CC];
__device__ float g_o [(size_t)BB*NTOK*CC];
__device__ float g_x2[(size_t)BB*NTOK*CC];
__device__ float g_f [(size_t)BB*NTOK*HIDD];
__device__ float g_g [(size_t)BB*NTOK*HIDD];
__device__ float g_convp[(size_t)8*NPATCH*CC]; // split-K conv partials
__device__ float g_xr[(size_t)NPATCH*CC];
__device__ float g_kv[(size_t)NPATCH*2*CC];

// ---------------- LayerNorm over rows of 64 ----------------
__global__ void __launch_bounds__(256) ln64_kernel(
    const float* __restrict__ in, float* __restrict__ out,
    const float* __restrict__ gamma, const float* __restrict__ beta, int nrows)
{
    int row = blockIdx.x * 8 + threadIdx.y;
    if (row >= nrows) return;
    int lane = threadIdx.x;
    float2 v = ((const float2*)(in + (size_t)row * 64))[lane];
    float s = v.x + v.y;
    #pragma unroll
    for (int o = 16; o; o >>= 1) s += __shfl_xor_sync(0xffffffffu, s, o);
    float mean = s * (1.0f / 64.0f);
    float dx = v.x - mean, dy = v.y - mean;
    float vs = dx * dx + dy * dy;
    #pragma unroll
    for (int o = 16; o; o >>= 1) vs += __shfl_xor_sync(0xffffffffu, vs, o);
    float rstd = rsqrtf(vs * (1.0f / 64.0f) + 1e-5f);
    float2 gg = ((const float2*)gamma)[lane];
    float2 bb = ((const float2*)beta)[lane];
    float2 r; r.x = dx * rstd * gg.x + bb.x; r.y = dy * rstd * gg.y + bb.y;
    ((float2*)(out + (size_t)row * 64))[lane] = r;
}

// ---------------- srn: sum conv partials + bias, then LN ----------------
__global__ void __launch_bounds__(256) srn_ln_kernel(
    const float* __restrict__ part, const float* __restrict__ srb,
    const float* __restrict__ gamma, const float* __restrict__ beta,
    float* __restrict__ out)
{
    int row = blockIdx.x * 8 + threadIdx.y;   // 0..2047
    int lane = threadIdx.x;
    float2 v = make_float2(0.f, 0.f);
    #pragma unroll
    for (int s = 0; s < 8; s++) {
        float2 p = ((const float2*)(part + ((size_t)s * NPATCH + row) * 64))[lane];
        v.x += p.x; v.y += p.y;
    }
    float2 sb = ((const float2*)srb)[lane];
    v.x += sb.x; v.y += sb.y;
    float s = v.x + v.y;
    #pragma unroll
    for (int o = 16; o; o >>= 1) s += __shfl_xor_sync(0xffffffffu, s, o);
    float mean = s * (1.0f / 64.0f);
    float dx = v.x - mean, dy = v.y - mean;
    float vs = dx * dx + dy * dy;
    #pragma unroll
    for (int o = 16; o; o >>= 1) vs += __shfl_xor_sync(0xffffffffu, vs, o);
    float rstd = rsqrtf(vs * (1.0f / 64.0f) + 1e-5f);
    float2 gg = ((const float2*)gamma)[lane];
    float2 bb = ((const float2*)beta)[lane];
    float2 r; r.x = dx * rstd * gg.x + bb.x; r.y = dy * rstd * gg.y + bb.y;
    ((float2*)(out + (size_t)row * 64))[lane] = r;
}

// ---------------- generic GEMM: out[M,ND] = A[M,KD] @ W[KD,ND] + bias (+resid) ----------------
// 64 rows per block, 256 threads, 4x(4*NJ) microtile, W fully smem-resident.
template<int KD, int ND, int NJ>
__global__ void __launch_bounds__(256) gemm_kernel(
    const float* __restrict__ A, const float* __restrict__ W,
    const float* __restrict__ bias, const float* __restrict__ resid,
    float* __restrict__ out)
{
    extern __shared__ float sm[];
    float* Ws = sm;                 // KD*ND
    float* As = sm + KD * ND;       // 64 x 68
    int t = threadIdx.x;
    int tx = t & 15, ty = t >> 4;
    size_t rowbase = (size_t)blockIdx.x * 64;

    for (int i = t * 4; i < KD * ND; i += 256 * 4)
        *(float4*)(Ws + i) = *(const float4*)(W + i);

    float acc[4][4 * NJ];
    #pragma unroll
    for (int m = 0; m < 4; m++)
        #pragma unroll
        for (int j = 0; j < 4 * NJ; j++) acc[m][j] = 0.f;

    for (int kc = 0; kc < KD; kc += 64) {
        __syncthreads();
        for (int i = t; i < 1024; i += 256) {       // 64 rows x 16 float4
            int r = i >> 4, c4 = i & 15;
            *(float4*)(As + r * 68 + c4 * 4) =
                *(const float4*)(A + (rowbase + r) * KD + kc + c4 * 4);
        }
        __syncthreads();
        #pragma unroll 8
        for (int k = 0; k < 64; k++) {
            float a[4], b[4 * NJ];
            #pragma unroll
            for (int m = 0; m < 4; m++) a[m] = As[(ty * 4 + m) * 68 + k];
            #pragma unroll
            for (int j = 0; j < NJ; j++)
                *(float4*)(b + j * 4) = *(float4*)(Ws + (kc + k) * ND + tx * 4 + j * 64);
            #pragma unroll
            for (int m = 0; m < 4; m++)
                #pragma unroll
                for (int j = 0; j < 4 * NJ; j++)
                    acc[m][j] = fmaf(a[m], b[j], acc[m][j]);
        }
    }

    #pragma unroll
    for (int m = 0; m < 4; m++) {
        size_t row = rowbase + ty * 4 + m;
        #pragma unroll
        for (int j = 0; j < NJ; j++) {
            int col = tx * 4 + j * 64;
            float4 r4;
            float* pa = &acc[m][j * 4];
            r4.x = pa[0] + bias[col + 0];
            r4.y = pa[1] + bias[col + 1];
            r4.z = pa[2] + bias[col + 2];
            r4.w = pa[3] + bias[col + 3];
            if (resid) {
                float4 rr = *(const float4*)(resid + row * ND + col);
                r4.x += rr.x; r4.y += rr.y; r4.z += rr.z; r4.w += rr.w;
            }
            *(float4*)(out + row * ND + col) = r4;
        }
    }
}

// ---------------- sr conv as split-K GEMM: grid (32 patch-tiles, 8 k-slices) ----------------
__global__ void __launch_bounds__(256) conv_sr_kernel(
    const float* __restrict__ h, const float* __restrict__ w,
    float* __restrict__ part)
{
    extern __shared__ float sm[];
    float* Ws = sm;            // 64 x 64
    float* As = sm + 4096;     // 64 x 68
    int t = threadIdx.x;
    int tx = t & 15, ty = t >> 4;
    int r1 = blockIdx.y;
    int pbase = blockIdx.x * 64;

    float acc[4][4];
    #pragma unroll
    for (int m = 0; m < 4; m++)
        #pragma unroll
        for (int j = 0; j < 4; j++) acc[m][j] = 0.f;

    for (int kk = 0; kk < 8; kk++) {
        __syncthreads();
        for (int i = t * 4; i < 4096; i += 1024)
            *(float4*)(Ws + i) = *(const float4*)(w + ((size_t)(r1 * 512 + kk * 64)) * 64 + i);
        for (int i = t; i < 1024; i += 256) {
            int r = i >> 4, c4 = i & 15;
            int p = pbase + r;
            int b = p >> 8, ph = (p >> 4) & 15, pw = p & 15;
            size_t base = ((size_t)b * NTOK + (size_t)(ph * 8 + r1) * 128 + pw * 8) * 64;
            *(float4*)(As + r * 68 + c4 * 4) = *(const float4*)(h + base + kk * 64 + c4 * 4);
        }
        __syncthreads();
        #pragma unroll 8
        for (int k = 0; k < 64; k++) {
            float a[4], b[4];
            #pragma unroll
            for (int m = 0; m < 4; m++) a[m] = As[(ty * 4 + m) * 68 + k];
            *(float4*)b = *(float4*)(Ws + k * 64 + tx * 4);
            #pragma unroll
            for (int m = 0; m < 4; m++)
                #pragma unroll
                for (int j = 0; j < 4; j++)
                    acc[m][j] = fmaf(a[m], b[j], acc[m][j]);
        }
    }
    #pragma unroll
    for (int m = 0; m < 4; m++) {
        int p = pbase + ty * 4 + m;
        float4 r4; r4.x = acc[m][0]; r4.y = acc[m][1]; r4.z = acc[m][2]; r4.w = acc[m][3];
        *(float4*)(part + ((size_t)r1 * NPATCH + p) * 64 + tx * 4) = r4;
    }
}

// ---------------- fused attention: 64 q-rows per block, K/V/Q/P smem-resident ----------------
#define KSS 65
#define VSS 68
#define SSS 260
__global__ void __launch_bounds__(512) attn_kernel(
    const float* __restrict__ q, const float* __restrict__ kv,
    float* __restrict__ o)
{
    extern __shared__ float sm[];
    float* Ks = sm;                       // 256*65
    float* Vs = Ks + 256 * KSS;           // 256*68
    float* Qs = Vs + 256 * VSS;           // 64*64
    float* Ss = Qs + 64 * 64;             // 64*260
    int t = threadIdx.x;
    int b = blockIdx.y;
    size_t qbase = ((size_t)b * NTOK + (size_t)blockIdx.x * 64) * 64;
    const float* kvb = kv + (size_t)b * NRTOK * 128;

    // load K (scalar, stride 65)
    for (int i = t; i < 16384; i += 512) {
        int m = i >> 6, c = i & 63;
        Ks[m * KSS + c] = kvb[m * 128 + c];
    }
    // load V (float4, stride 68)
    for (int i = t; i < 4096; i += 512) {
        int m = i >> 4, c4 = i & 15;
        *(float4*)(Vs + m * VSS + c4 * 4) = *(const float4*)(kvb + m * 128 + 64 + c4 * 4);
    }
    // load Q pre-scaled by 1/sqrt(hd)
    for (int i = t; i < 1024; i += 512) {
        float4 qv = *(const float4*)(q + qbase + (size_t)i * 4);
        qv.x *= 0.125f; qv.y *= 0.125f; qv.z *= 0.125f; qv.w *= 0.125f;
        *(float4*)(Qs + i * 4) = qv;
    }
    __syncthreads();

    // ---- S = Q @ K^T : warp ty owns rows ty*4..+3; lane tx owns m = tx+32j ----
    int tx = t & 31, ty = t >> 5;
    float s[4][8];
    #pragma unroll
    for (int m = 0; m < 4; m++)
        #pragma unroll
        for (int j = 0; j < 8; j++) s[m][j] = 0.f;
    #pragma unroll 8
    for (int k = 0; k < 64; k++) {
        float a[4], bfr[8];
        #pragma unroll
        for (int m = 0; m < 4; m++) a[m] = Qs[(ty * 4 + m) * 64 + k];
        #pragma unroll
        for (int j = 0; j < 8; j++) bfr[j] = Ks[(tx + 32 * j) * KSS + k];
        #pragma unroll
        for (int m = 0; m < 4; m++)
            #pragma unroll
            for (int j = 0; j < 8; j++)
                s[m][j] = fmaf(a[m], bfr[j], s[m][j]);
    }

    // ---- softmax per row, entirely within the warp ----
    #pragma unroll
    for (int m = 0; m < 4; m++) {
        float mx = s[m][0];
        #pragma unroll
        for (int j = 1; j < 8; j++) mx = fmaxf(mx, s[m][j]);
        #pragma unroll
        for (int off = 16; off; off >>= 1) mx = fmaxf(mx, __shfl_xor_sync(0xffffffffu, mx, off));
        float sum = 0.f;
        #pragma unroll
        for (int j = 0; j < 8; j++) { s[m][j] = __expf(s[m][j] - mx); sum += s[m][j]; }
        #pragma unroll
        for (int off = 16; off; off >>= 1) sum += __shfl_xor_sync(0xffffffffu, sum, off);
        float inv = __frcp_rn(sum);
        #pragma unroll
        for (int j = 0; j < 8; j++) s[m][j] *= inv;
    }
    // write P to smem
    #pragma unroll
    for (int m = 0; m < 4; m++)
        #pragma unroll
        for (int j = 0; j < 8; j++)
            Ss[(ty * 4 + m) * SSS + tx + 32 * j] = s[m][j];
    __syncthreads();

    // ---- O = P @ V : thread owns rows rg*2..+1, cols txd*4..+3 ----
    int txd = t & 15, rg = t >> 4;
    float acc0[4] = {0.f, 0.f, 0.f, 0.f};
    float acc1[4] = {0.f, 0.f, 0.f, 0.f};
    #pragma unroll 4
    for (int m = 0; m < 256; m++) {
        float a0 = Ss[(rg * 2) * SSS + m];
        float a1 = Ss[(rg * 2 + 1) * SSS + m];
        float4 bv = *(float4*)(Vs + m * VSS + txd * 4);
        acc0[0] = fmaf(a0, bv.x, acc0[0]); acc0[1] = fmaf(a0, bv.y, acc0[1]);
        acc0[2] = fmaf(a0, bv.z, acc0[2]); acc0[3] = fmaf(a0, bv.w, acc0[3]);
        acc1[0] = fmaf(a1, bv.x, acc1[0]); acc1[1] = fmaf(a1, bv.y, acc1[1]);
        acc1[2] = fmaf(a1, bv.z, acc1[2]); acc1[3] = fmaf(a1, bv.w, acc1[3]);
    }
    size_t obase = ((size_t)b * NTOK + (size_t)blockIdx.x * 64) * 64;
    float4 w0; w0.x = acc0[0]; w0.y = acc0[1]; w0.z = acc0[2]; w0.w = acc0[3];
    float4 w1; w1.x = acc1[0]; w1.y = acc1[1]; w1.z = acc1[2]; w1.w = acc1[3];
    *(float4*)(o + obase + (size_t)(rg * 2) * 64 + txd * 4) = w0;
    *(float4*)(o + obase + (size_t)(rg * 2 + 1) * 64 + txd * 4) = w1;
}

// ---------------- depthwise 3x3 SAME + exact GELU ----------------
__global__ void __launch_bounds__(256) dwconv_gelu_kernel(
    const float* __restrict__ f, const float* __restrict__ w,
    float* __restrict__ g)
{
    size_t id = (size_t)blockIdx.x * 256 + threadIdx.x;
    int c  = (int)(id & 255);
    int xg = (int)((id >> 8) & 31);
    int y  = (int)((id >> 13) & 127);
    int b  = (int)(id >> 20);
    int x0 = xg * 4;
    const float* fb = f + (size_t)b * NTOK * 256;
    float wv[9];
    #pragma unroll
    for (int i = 0; i < 9; i++) wv[i] = w[i * 256 + c];
    float acc[4] = {0.f, 0.f, 0.f, 0.f};
    #pragma unroll
    for (int dy = -1; dy <= 1; dy++) {
        int yy = y + dy;
        if (yy < 0 || yy > 127) continue;
        const float* rowp = fb + (size_t)yy * 128 * 256 + c;
        float vb[6];
        #pragma unroll
        for (int xx = 0; xx < 6; xx++) {
            int xa = x0 - 1 + xx;
            vb[xx] = (xa >= 0 && xa < 128) ? rowp[(size_t)xa * 256] : 0.f;
        }
        int wr = (dy + 1) * 3;
        #pragma unroll
        for (int xi = 0; xi < 4; xi++)
            #pragma unroll
            for (int dx = 0; dx < 3; dx++)
                acc[xi] = fmaf(vb[xi + dx], wv[wr + dx], acc[xi]);
    }
    #pragma unroll
    for (int xi = 0; xi < 4; xi++) {
        float v = acc[xi];
        v = 0.5f * v * (1.0f + erff(v * 0.70710678118654752f));
        g[((size_t)b * NTOK + (size_t)y * 128 + x0 + xi) * 256 + c] = v;
    }
}

// ---------------- launch ----------------
extern "C" void kernel_launch(void* const* d_in, const int* in_sizes, int n_in,
                              void* d_out, int out_size)
{
    const float* x      = (const float*)d_in[0];
    const float* ln1_g  = (const float*)d_in[3];
    const float* ln1_b  = (const float*)d_in[4];
    const float* q_w    = (const float*)d_in[5];
    const float* q_b    = (const float*)d_in[6];
    const float* kv_w   = (const float*)d_in[7];
    const float* kv_b   = (const float*)d_in[8];
    const float* proj_w = (const float*)d_in[9];
    const float* proj_b = (const float*)d_in[10];
    const float* sr_w   = (const float*)d_in[11];
    const float* sr_b   = (const float*)d_in[12];
    const float* srn_g  = (const float*)d_in[13];
    const float* srn_b  = (const float*)d_in[14];
    const float* ln2_g  = (const float*)d_in[15];
    const float* ln2_b  = (const float*)d_in[16];
    const float* fc1_w  = (const float*)d_in[17];
    const float* fc1_b  = (const float*)d_in[18];
    const float* dw_w   = (const float*)d_in[19];
    const float* fc2_w  = (const float*)d_in[20];
    const float* fc2_b  = (const float*)d_in[21];
    float* out = (float*)d_out;

    float *h, *q, *o, *x2, *f, *g, *convp, *xr, *kvb;
    cudaGetSymbolAddress((void**)&h,     g_h);
    cudaGetSymbolAddress((void**)&q,     g_q);
    cudaGetSymbolAddress((void**)&o,     g_o);
    cudaGetSymbolAddress((void**)&x2,    g_x2);
    cudaGetSymbolAddress((void**)&f,     g_f);
    cudaGetSymbolAddress((void**)&g,     g_g);
    cudaGetSymbolAddress((void**)&convp, g_convp);
    cudaGetSymbolAddress((void**)&xr,    g_xr);
    cudaGetSymbolAddress((void**)&kvb,   g_kv);

    const int SM_G64  = (64 * 64 + 64 * 68) * 4;      // 33792
    const int SM_G128 = (64 * 128 + 64 * 68) * 4;     // 50176
    const int SM_G256 = (64 * 256 + 64 * 68) * 4;     // 82944
    const int SM_ATTN = (256 * KSS + 256 * VSS + 64 * 64 + 64 * SSS) * 4; // 219136

    cudaFuncSetAttribute((const void*)gemm_kernel<64, 128, 2>,
                         cudaFuncAttributeMaxDynamicSharedMemorySize, SM_G128);
    cudaFuncSetAttribute((const void*)gemm_kernel<64, 256, 4>,
                         cudaFuncAttributeMaxDynamicSharedMemorySize, SM_G256);
    cudaFuncSetAttribute((const void*)gemm_kernel<256, 64, 1>,
                         cudaFuncAttributeMaxDynamicSharedMemorySize, SM_G256);
    cudaFuncSetAttribute((const void*)attn_kernel,
                         cudaFuncAttributeMaxDynamicSharedMemorySize, SM_ATTN);

    dim3 lnb(32, 8);
    // 1) h = LN1(x)
    ln64_kernel<<<16384, lnb>>>(x, h, ln1_g, ln1_b, BB * NTOK);
    // 2) q = h @ q_w + q_b
    gemm_kernel<64, 64, 1><<<2048, 256, SM_G64>>>(h, q_w, q_b, nullptr, q);
    // 3) sr conv partials (split-K over the 8 patch rows)
    conv_sr_kernel<<<dim3(32, 8), 256, SM_G64>>>(h, sr_w, convp);
    // 4) xr = LN(sum partials + sr_b)
    srn_ln_kernel<<<256, lnb>>>(convp, sr_b, srn_g, srn_b, xr);
    // 5) kv = xr @ kv_w + kv_b
    gemm_kernel<64, 128, 2><<<32, 256, SM_G128>>>(xr, kv_w, kv_b, nullptr, kvb);
    // 6) o = softmax(q k^T * scale) v
    attn_kernel<<<dim3(256, BB), 512, SM_ATTN>>>(q, kvb, o);
    // 7) x2 = x + o @ proj_w + proj_b
    gemm_kernel<64, 64, 1><<<2048, 256, SM_G64>>>(o, proj_w, proj_b, x, x2);
    // 8) h = LN2(x2)   (reuse h buffer)
    ln64_kernel<<<16384, lnb>>>(x2, h, ln2_g, ln2_b, BB * NTOK);
    // 9) f = h @ fc1_w + fc1_b
    gemm_kernel<64, 256, 4><<<2048, 256, SM_G256>>>(h, fc1_w, fc1_b, nullptr, f);
    // 10) g = gelu(dwconv3x3(f))
    dwconv_gelu_kernel<<<32768, 256>>>(f, dw_w, g);
    // 11) out = x2 + g @ fc2_w + fc2_b
    gemm_kernel<256, 64, 1><<<2048, 256, SM_G256>>>(g, fc2_w, fc2_b, x2, out);
}

// round 2
// speedup vs baseline: 2.7174x; 2.7174x over previous
#include <cuda_runtime.h>
#include <cuda_bf16.h>
#include <math.h>
#include <stdint.h>

typedef __nv_bfloat16 bf16;

// ---------------- static shapes ----------------
#define BB    8
#define NTOK  16384
#define CC    64
#define HIDD  256
#define NRTOK 256
#define MTOT  (BB*NTOK)   // 131072

// ---------------- scratch ----------------
__device__ bf16  g_hb [(size_t)MTOT*CC];
__device__ bf16  g_qb [(size_t)MTOT*CC];
__device__ bf16  g_ob [(size_t)MTOT*CC];
__device__ float g_x2 [(size_t)MTOT*CC];
__device__ bf16  g_fb [(size_t)MTOT*HIDD];
__device__ bf16  g_gb [(size_t)MTOT*HIDD];
__device__ float g_convp[(size_t)8*2048*CC];
__device__ bf16  g_xrb[(size_t)2048*CC];
__device__ bf16  g_kvb[(size_t)2048*2*CC];
__device__ bf16  g_wq [64*64];
__device__ bf16  g_wkv[64*128];
__device__ bf16  g_wp [64*64];
__device__ bf16  g_wsr[4096*64];
__device__ bf16  g_w1 [64*256];
__device__ bf16  g_w2 [256*64];

// ---------------- mma / ldmatrix helpers ----------------
__device__ __forceinline__ void mma_bf16(float& d0,float& d1,float& d2,float& d3,
    uint32_t a0,uint32_t a1,uint32_t a2,uint32_t a3,uint32_t b0,uint32_t b1){
  asm volatile("mma.sync.aligned.m16n8k16.row.col.f32.bf16.bf16.f32 "
    "{%0,%1,%2,%3}, {%4,%5,%6,%7}, {%8,%9}, {%0,%1,%2,%3};\n"
    : "+f"(d0),"+f"(d1),"+f"(d2),"+f"(d3)
    : "r"(a0),"r"(a1),"r"(a2),"r"(a3),"r"(b0),"r"(b1));
}
__device__ __forceinline__ void ldsm_x4(uint32_t* r, uint32_t addr){
  asm volatile("ldmatrix.sync.aligned.m8n8.x4.shared.b16 {%0,%1,%2,%3}, [%4];\n"
    : "=r"(r[0]),"=r"(r[1]),"=r"(r[2]),"=r"(r[3]) : "r"(addr));
}
__device__ __forceinline__ void ldsm_x4_t(uint32_t* r, uint32_t addr){
  asm volatile("ldmatrix.sync.aligned.m8n8.x4.trans.shared.b16 {%0,%1,%2,%3}, [%4];\n"
    : "=r"(r[0]),"=r"(r[1]),"=r"(r[2]),"=r"(r[3]) : "r"(addr));
}
__device__ __forceinline__ uint32_t pack2(float lo, float hi){
  __nv_bfloat162 v = __floats2bfloat162_rn(lo, hi);
  return reinterpret_cast<uint32_t&>(v);
}

// ---------------- fp32 -> bf16 weight conversion ----------------
__global__ void __launch_bounds__(256) cvt_kernel(const float* __restrict__ in,
                                                  bf16* __restrict__ out, int n){
  int i = blockIdx.x*256 + threadIdx.x;
  if (i < n) out[i] = __float2bfloat16(in[i]);
}

// ---------------- LayerNorm (fp32 in, bf16 out) ----------------
__global__ void __launch_bounds__(256) ln64_kernel(
    const float* __restrict__ in, bf16* __restrict__ out,
    const float* __restrict__ gamma, const float* __restrict__ beta, int nrows)
{
  int row = blockIdx.x*8 + threadIdx.y;
  if (row >= nrows) return;
  int lane = threadIdx.x;
  float2 v = ((const float2*)(in + (size_t)row*64))[lane];
  float s = v.x + v.y;
  #pragma unroll
  for (int o = 16; o; o >>= 1) s += __shfl_xor_sync(0xffffffffu, s, o);
  float mean = s * (1.0f/64.0f);
  float dx = v.x - mean, dy = v.y - mean;
  float vs = dx*dx + dy*dy;
  #pragma unroll
  for (int o = 16; o; o >>= 1) vs += __shfl_xor_sync(0xffffffffu, vs, o);
  float rstd = rsqrtf(vs*(1.0f/64.0f) + 1e-5f);
  float2 gg = ((const float2*)gamma)[lane];
  float2 bb = ((const float2*)beta)[lane];
  ((uint32_t*)(out + (size_t)row*64))[lane] =
      pack2(dx*rstd*gg.x + bb.x, dy*rstd*gg.y + bb.y);
}

// ---------------- srn: sum conv partials + bias, LN, bf16 out ----------------
__global__ void __launch_bounds__(256) srn_ln_kernel(
    const float* __restrict__ part, const float* __restrict__ srb,
    const float* __restrict__ gamma, const float* __restrict__ beta,
    bf16* __restrict__ out)
{
  int row = blockIdx.x*8 + threadIdx.y;
  int lane = threadIdx.x;
  float2 v = make_float2(0.f, 0.f);
  #pragma unroll
  for (int s = 0; s < 8; s++){
    float2 p = ((const float2*)(part + ((size_t)s*2048 + row)*64))[lane];
    v.x += p.x; v.y += p.y;
  }
  float2 sb = ((const float2*)srb)[lane];
  v.x += sb.x; v.y += sb.y;
  float s = v.x + v.y;
  #pragma unroll
  for (int o = 16; o; o >>= 1) s += __shfl_xor_sync(0xffffffffu, s, o);
  float mean = s * (1.0f/64.0f);
  float dx = v.x - mean, dy = v.y - mean;
  float vs = dx*dx + dy*dy;
  #pragma unroll
  for (int o = 16; o; o >>= 1) vs += __shfl_xor_sync(0xffffffffu, vs, o);
  float rstd = rsqrtf(vs*(1.0f/64.0f) + 1e-5f);
  float2 gg = ((const float2*)gamma)[lane];
  float2 bb = ((const float2*)beta)[lane];
  ((uint32_t*)(out + (size_t)row*64))[lane] =
      pack2(dx*rstd*gg.x + bb.x, dy*rstd*gg.y + bb.y);
}

// ---------------- generic bf16 tensor-core GEMM ----------------
// out[M, NSRC](cols [col0,col0+ND)) = (A[M,KD] @ W[KD,NSRC][:,col0:..] + bias)*oscale (+resid)
// M tile 128, 8 warps (warp w -> rows 16w..16w+15), all ND cols per warp.
template<int KD, int ND, int NSRC, bool OUTBF>
__global__ void __launch_bounds__(256) gemm_mma(
    const bf16* __restrict__ A, const bf16* __restrict__ W,
    const float* __restrict__ bias, const float* __restrict__ resid,
    float* __restrict__ outF, bf16* __restrict__ outB, float oscale)
{
  constexpr int WSTR = ND + 8;
  constexpr int ASTR = 72;
  extern __shared__ bf16 smg[];
  bf16* Ws = smg;
  bf16* As = smg + KD*WSTR;
  int t = threadIdx.x, w = t>>5, lane = t&31;
  int col0 = blockIdx.y * ND;
  size_t rowbase = (size_t)blockIdx.x * 128;

  for (int i = t; i < KD*(ND/8); i += 256){
    int row = i/(ND/8), c8 = i%(ND/8);
    *(float4*)(Ws + row*WSTR + c8*8) = *(const float4*)(W + (size_t)row*NSRC + col0 + c8*8);
  }

  float acc[ND/8][4];
  #pragma unroll
  for (int nb = 0; nb < ND/8; nb++){ acc[nb][0]=acc[nb][1]=acc[nb][2]=acc[nb][3]=0.f; }

  uint32_t As_u = (uint32_t)__cvta_generic_to_shared(As);
  uint32_t Ws_u = (uint32_t)__cvta_generic_to_shared(Ws);
  uint32_t a_base = As_u + ((w*16 + (lane&15))*ASTR + (lane>>4)*8)*2;
  uint32_t b_off  = (lane&15)*WSTR*2 + (lane>>4)*16;

  for (int kc = 0; kc < KD; kc += 64){
    __syncthreads();
    for (int i = t; i < 1024; i += 256){
      int r = i>>3, c8 = i&7;
      *(float4*)(As + r*ASTR + c8*8) = *(const float4*)(A + (rowbase + r)*KD + kc + c8*8);
    }
    __syncthreads();
    #pragma unroll
    for (int kb = 0; kb < 4; kb++){
      uint32_t a[4];
      ldsm_x4(a, a_base + kb*32);
      uint32_t brow = Ws_u + (uint32_t)(kc + kb*16)*WSTR*2 + b_off;
      #pragma unroll
      for (int nb2 = 0; nb2 < ND/16; nb2++){
        uint32_t b[4];
        ldsm_x4_t(b, brow + nb2*32);
        mma_bf16(acc[2*nb2  ][0],acc[2*nb2  ][1],acc[2*nb2  ][2],acc[2*nb2  ][3],
                 a[0],a[1],a[2],a[3], b[0],b[1]);
        mma_bf16(acc[2*nb2+1][0],acc[2*nb2+1][1],acc[2*nb2+1][2],acc[2*nb2+1][3],
                 a[0],a[1],a[2],a[3], b[2],b[3]);
      }
    }
  }

  int g = lane>>2, tq = lane&3;
  size_t r0 = rowbase + w*16 + g, r1 = r0 + 8;
  #pragma unroll
  for (int nb = 0; nb < ND/8; nb++){
    int col = col0 + nb*8 + tq*2;
    float b0 = bias[col], b1 = bias[col+1];
    float v00 = (acc[nb][0] + b0)*oscale, v01 = (acc[nb][1] + b1)*oscale;
    float v10 = (acc[nb][2] + b0)*oscale, v11 = (acc[nb][3] + b1)*oscale;
    if (resid){
      float2 q0 = *(const float2*)(resid + r0*NSRC + col);
      float2 q1 = *(const float2*)(resid + r1*NSRC + col);
      v00 += q0.x; v01 += q0.y; v10 += q1.x; v11 += q1.y;
    }
    if (OUTBF){
      *(uint32_t*)(outB + r0*NSRC + col) = pack2(v00, v01);
      *(uint32_t*)(outB + r1*NSRC + col) = pack2(v10, v11);
    } else {
      *(float2*)(outF + r0*NSRC + col) = make_float2(v00, v01);
      *(float2*)(outF + r1*NSRC + col) = make_float2(v10, v11);
    }
  }
}

// ---------------- sr conv as split-K mma GEMM ----------------
__global__ void __launch_bounds__(256) conv_mma(
    const bf16* __restrict__ h, const bf16* __restrict__ wsr,
    float* __restrict__ part)
{
  __shared__ bf16 Ws[64*72];
  __shared__ bf16 As[128*72];
  int t = threadIdx.x, w = t>>5, lane = t&31;
  int r1 = blockIdx.y;
  int pbase = blockIdx.x * 128;

  float acc[8][4];
  #pragma unroll
  for (int nb = 0; nb < 8; nb++){ acc[nb][0]=acc[nb][1]=acc[nb][2]=acc[nb][3]=0.f; }

  uint32_t As_u = (uint32_t)__cvta_generic_to_shared(As);
  uint32_t Ws_u = (uint32_t)__cvta_generic_to_shared(Ws);
  uint32_t a_base = As_u + ((w*16 + (lane&15))*72 + (lane>>4)*8)*2;
  uint32_t b_off  = (lane&15)*144 + (lane>>4)*16;

  for (int kk = 0; kk < 8; kk++){
    __syncthreads();
    for (int i = t; i < 512; i += 256){
      int row = i>>3, c8 = i&7;
      *(float4*)(Ws + row*72 + c8*8) =
        *(const float4*)(wsr + ((size_t)(r1*512 + kk*64 + row))*64 + c8*8);
    }
    for (int i = t; i < 1024; i += 256){
      int r = i>>3, c8 = i&7;
      int p = pbase + r;
      int b = p>>8, ph = (p>>4)&15, pw = p&15;
      size_t src = ((((size_t)b*128 + ph*8 + r1)*128) + pw*8)*64 + kk*64 + c8*8;
      *(float4*)(As + r*72 + c8*8) = *(const float4*)(h + src);
    }
    __syncthreads();
    #pragma unroll
    for (int kb = 0; kb < 4; kb++){
      uint32_t a[4];
      ldsm_x4(a, a_base + kb*32);
      uint32_t brow = Ws_u + (uint32_t)(kb*16)*144 + b_off;
      #pragma unroll
      for (int nb2 = 0; nb2 < 4; nb2++){
        uint32_t b[4];
        ldsm_x4_t(b, brow + nb2*32);
        mma_bf16(acc[2*nb2  ][0],acc[2*nb2  ][1],acc[2*nb2  ][2],acc[2*nb2  ][3],
                 a[0],a[1],a[2],a[3], b[0],b[1]);
        mma_bf16(acc[2*nb2+1][0],acc[2*nb2+1][1],acc[2*nb2+1][2],acc[2*nb2+1][3],
                 a[0],a[1],a[2],a[3], b[2],b[3]);
      }
    }
  }
  int g = lane>>2, tq = lane&3;
  size_t p0 = pbase + w*16 + g, p1 = p0 + 8;
  #pragma unroll
  for (int nb = 0; nb < 8; nb++){
    int col = nb*8 + tq*2;
    *(float2*)(part + ((size_t)r1*2048 + p0)*64 + col) = make_float2(acc[nb][0], acc[nb][1]);
    *(float2*)(part + ((size_t)r1*2048 + p1)*64 + col) = make_float2(acc[nb][2], acc[nb][3]);
  }
}

// ---------------- fused attention (tensor-core, softmax in registers) ----------------
__global__ void __launch_bounds__(256) attn_mma(
    const bf16* __restrict__ q, const bf16* __restrict__ kv, bf16* __restrict__ o)
{
  extern __shared__ bf16 sma[];
  bf16* Qs = sma;              // 128 x 72
  bf16* Ks = sma + 128*72;     // 256 x 72
  bf16* Vs = Ks  + 256*72;     // 256 x 72
  int t = threadIdx.x, w = t>>5, lane = t&31;
  int b = blockIdx.y;
  size_t qrow0 = (size_t)b*NTOK + (size_t)blockIdx.x*128;
  const bf16* kvb = kv + (size_t)b*NRTOK*128;

  for (int i = t; i < 1024; i += 256){
    int r = i>>3, c8 = i&7;
    *(float4*)(Qs + r*72 + c8*8) = *(const float4*)(q + (qrow0 + r)*64 + c8*8);
  }
  for (int i = t; i < 2048; i += 256){
    int r = i>>3, c8 = i&7;
    *(float4*)(Ks + r*72 + c8*8) = *(const float4*)(kvb + (size_t)r*128 + c8*8);
  }
  for (int i = t; i < 2048; i += 256){
    int r = i>>3, c8 = i&7;
    *(float4*)(Vs + r*72 + c8*8) = *(const float4*)(kvb + (size_t)r*128 + 64 + c8*8);
  }
  __syncthreads();

  uint32_t Qs_u = (uint32_t)__cvta_generic_to_shared(Qs);
  uint32_t Ks_u = (uint32_t)__cvta_generic_to_shared(Ks);
  uint32_t Vs_u = (uint32_t)__cvta_generic_to_shared(Vs);
  uint32_t a_base = Qs_u + ((w*16 + (lane&15))*72 + (lane>>4)*8)*2;
  // non-trans B (keys x dim row-major): rows by n, 16B halves by k
  uint32_t k_off = ((((lane>>4)&1)*8 + (lane&7)))*144 + ((lane>>3)&1)*16;
  uint32_t v_off = (lane&15)*144 + (lane>>4)*16;

  float s[32][4];
  #pragma unroll
  for (int nb = 0; nb < 32; nb++){ s[nb][0]=s[nb][1]=s[nb][2]=s[nb][3]=0.f; }

  // ---- S = Qs @ Ks^T (16 rows x 256 keys per warp) ----
  #pragma unroll
  for (int kb = 0; kb < 4; kb++){
    uint32_t a[4];
    ldsm_x4(a, a_base + kb*32);
    #pragma unroll
    for (int ng = 0; ng < 16; ng++){
      uint32_t bb[4];
      ldsm_x4(bb, Ks_u + (uint32_t)ng*2304 + kb*32 + k_off);
      mma_bf16(s[2*ng  ][0],s[2*ng  ][1],s[2*ng  ][2],s[2*ng  ][3],
               a[0],a[1],a[2],a[3], bb[0],bb[1]);
      mma_bf16(s[2*ng+1][0],s[2*ng+1][1],s[2*ng+1][2],s[2*ng+1][3],
               a[0],a[1],a[2],a[3], bb[2],bb[3]);
    }
  }

  // ---- softmax over 256 keys (rows g and g+8) ----
  float mx0 = -1e30f, mx1 = -1e30f;
  #pragma unroll
  for (int nb = 0; nb < 32; nb++){
    mx0 = fmaxf(mx0, fmaxf(s[nb][0], s[nb][1]));
    mx1 = fmaxf(mx1, fmaxf(s[nb][2], s[nb][3]));
  }
  mx0 = fmaxf(mx0, __shfl_xor_sync(0xffffffffu, mx0, 1));
  mx0 = fmaxf(mx0, __shfl_xor_sync(0xffffffffu, mx0, 2));
  mx1 = fmaxf(mx1, __shfl_xor_sync(0xffffffffu, mx1, 1));
  mx1 = fmaxf(mx1, __shfl_xor_sync(0xffffffffu, mx1, 2));
  float sm0 = 0.f, sm1 = 0.f;
  #pragma unroll
  for (int nb = 0; nb < 32; nb++){
    s[nb][0] = __expf(s[nb][0] - mx0); sm0 += s[nb][0];
    s[nb][1] = __expf(s[nb][1] - mx0); sm0 += s[nb][1];
    s[nb][2] = __expf(s[nb][2] - mx1); sm1 += s[nb][2];
    s[nb][3] = __expf(s[nb][3] - mx1); sm1 += s[nb][3];
  }
  sm0 += __shfl_xor_sync(0xffffffffu, sm0, 1);
  sm0 += __shfl_xor_sync(0xffffffffu, sm0, 2);
  sm1 += __shfl_xor_sync(0xffffffffu, sm1, 1);
  sm1 += __shfl_xor_sync(0xffffffffu, sm1, 2);
  float inv0 = __frcp_rn(sm0), inv1 = __frcp_rn(sm1);
  #pragma unroll
  for (int nb = 0; nb < 32; nb++){
    s[nb][0] *= inv0; s[nb][1] *= inv0; s[nb][2] *= inv1; s[nb][3] *= inv1;
  }

  // ---- O = P @ V : c-frag of S reinterpreted as a-frag ----
  float oo[8][4];
  #pragma unroll
  for (int nb = 0; nb < 8; nb++){ oo[nb][0]=oo[nb][1]=oo[nb][2]=oo[nb][3]=0.f; }
  #pragma unroll
  for (int kb = 0; kb < 16; kb++){
    uint32_t a0 = pack2(s[2*kb  ][0], s[2*kb  ][1]);
    uint32_t a1 = pack2(s[2*kb  ][2], s[2*kb  ][3]);
    uint32_t a2 = pack2(s[2*kb+1][0], s[2*kb+1][1]);
    uint32_t a3 = pack2(s[2*kb+1][2], s[2*kb+1][3]);
    uint32_t base = Vs_u + (uint32_t)kb*16*144 + v_off;
    #pragma unroll
    for (int n2 = 0; n2 < 4; n2++){
      uint32_t bb[4];
      ldsm_x4_t(bb, base + n2*32);
      mma_bf16(oo[2*n2  ][0],oo[2*n2  ][1],oo[2*n2  ][2],oo[2*n2  ][3],
               a0,a1,a2,a3, bb[0],bb[1]);
      mma_bf16(oo[2*n2+1][0],oo[2*n2+1][1],oo[2*n2+1][2],oo[2*n2+1][3],
               a0,a1,a2,a3, bb[2],bb[3]);
    }
  }

  int g = lane>>2, tq = lane&3;
  size_t r0 = qrow0 + w*16 + g, r1 = r0 + 8;
  #pragma unroll
  for (int nb = 0; nb < 8; nb++){
    int col = nb*8 + tq*2;
    *(uint32_t*)(o + r0*64 + col) = pack2(oo[nb][0], oo[nb][1]);
    *(uint32_t*)(o + r1*64 + col) = pack2(oo[nb][2], oo[nb][3]);
  }
}

// ---------------- depthwise 3x3 SAME + exact GELU (bf16 io) ----------------
__global__ void __launch_bounds__(256) dwconv_gelu(
    const bf16* __restrict__ f, const float* __restrict__ w, bf16* __restrict__ g)
{
  size_t id = (size_t)blockIdx.x*256 + threadIdx.x;
  int c  = (int)(id & 255);
  int xg = (int)((id >> 8) & 31);
  int y  = (int)((id >> 13) & 127);
  int b  = (int)(id >> 20);
  int x0 = xg*4;
  const bf16* fb = f + (size_t)b*NTOK*256;
  float wv[9];
  #pragma unroll
  for (int i = 0; i < 9; i++) wv[i] = w[i*256 + c];
  float acc[4] = {0.f, 0.f, 0.f, 0.f};
  #pragma unroll
  for (int dy = -1; dy <= 1; dy++){
    int yy = y + dy;
    if (yy < 0 || yy > 127) continue;
    const bf16* rowp = fb + (size_t)yy*128*256 + c;
    float vb[6];
    #pragma unroll
    for (int xx = 0; xx < 6; xx++){
      int xa = x0 - 1 + xx;
      vb[xx] = (xa >= 0 && xa < 128) ? __bfloat162float(rowp[(size_t)xa*256]) : 0.f;
    }
    int wr = (dy+1)*3;
    #pragma unroll
    for (int xi = 0; xi < 4; xi++)
      #pragma unroll
      for (int dx = 0; dx < 3; dx++)
        acc[xi] = fmaf(vb[xi+dx], wv[wr+dx], acc[xi]);
  }
  #pragma unroll
  for (int xi = 0; xi < 4; xi++){
    float v = acc[xi];
    v = 0.5f*v*(1.0f + erff(v*0.70710678118654752f));
    g[((size_t)b*NTOK + (size_t)y*128 + x0 + xi)*256 + c] = __float2bfloat16(v);
  }
}

// ---------------- launch ----------------
extern "C" void kernel_launch(void* const* d_in, const int* in_sizes, int n_in,
                              void* d_out, int out_size)
{
  const float* x      = (const float*)d_in[0];
  const float* ln1_g  = (const float*)d_in[3];
  const float* ln1_b  = (const float*)d_in[4];
  const float* q_w    = (const float*)d_in[5];
  const float* q_b    = (const float*)d_in[6];
  const float* kv_w   = (const float*)d_in[7];
  const float* kv_b   = (const float*)d_in[8];
  const float* proj_w = (const float*)d_in[9];
  const float* proj_b = (const float*)d_in[10];
  const float* sr_w   = (const float*)d_in[11];
  const float* sr_b   = (const float*)d_in[12];
  const float* srn_g  = (const float*)d_in[13];
  const float* srn_b  = (const float*)d_in[14];
  const float* ln2_g  = (const float*)d_in[15];
  const float* ln2_b  = (const float*)d_in[16];
  const float* fc1_w  = (const float*)d_in[17];
  const float* fc1_b  = (const float*)d_in[18];
  const float* dw_w   = (const float*)d_in[19];
  const float* fc2_w  = (const float*)d_in[20];
  const float* fc2_b  = (const float*)d_in[21];
  float* out = (float*)d_out;

  bf16 *hb,*qb,*ob,*fb,*gb,*xrb,*kvb,*wq,*wkv,*wp,*wsr,*w1,*w2;
  float *x2,*convp;
  cudaGetSymbolAddress((void**)&hb,  g_hb);
  cudaGetSymbolAddress((void**)&qb,  g_qb);
  cudaGetSymbolAddress((void**)&ob,  g_ob);
  cudaGetSymbolAddress((void**)&x2,  g_x2);
  cudaGetSymbolAddress((void**)&fb,  g_fb);
  cudaGetSymbolAddress((void**)&gb,  g_gb);
  cudaGetSymbolAddress((void**)&convp, g_convp);
  cudaGetSymbolAddress((void**)&xrb, g_xrb);
  cudaGetSymbolAddress((void**)&kvb, g_kvb);
  cudaGetSymbolAddress((void**)&wq,  g_wq);
  cudaGetSymbolAddress((void**)&wkv, g_wkv);
  cudaGetSymbolAddress((void**)&wp,  g_wp);
  cudaGetSymbolAddress((void**)&wsr, g_wsr);
  cudaGetSymbolAddress((void**)&w1,  g_w1);
  cudaGetSymbolAddress((void**)&w2,  g_w2);

  const int SM_G64  = (64*72  + 128*72)*2;   // 27648
  const int SM_G128 = (64*136 + 128*72)*2;   // 35840
  const int SM_FC2  = (256*72 + 128*72)*2;   // 55296
  const int SM_ATTN = (128 + 256 + 256)*72*2;// 92160

  cudaFuncSetAttribute((const void*)gemm_mma<64,64,64,true>,
                       cudaFuncAttributeMaxDynamicSharedMemorySize, SM_G64);
  cudaFuncSetAttribute((const void*)gemm_mma<64,64,64,false>,
                       cudaFuncAttributeMaxDynamicSharedMemorySize, SM_G64);
  cudaFuncSetAttribute((const void*)gemm_mma<64,128,128,true>,
                       cudaFuncAttributeMaxDynamicSharedMemorySize, SM_G128);
  cudaFuncSetAttribute((const void*)gemm_mma<64,128,256,true>,
                       cudaFuncAttributeMaxDynamicSharedMemorySize, SM_G128);
  cudaFuncSetAttribute((const void*)gemm_mma<256,64,64,false>,
                       cudaFuncAttributeMaxDynamicSharedMemorySize, SM_FC2);
  cudaFuncSetAttribute((const void*)attn_mma,
                       cudaFuncAttributeMaxDynamicSharedMemorySize, SM_ATTN);

  // weight conversions
  cvt_kernel<<<16, 256>>>(q_w,   wq,  64*64);
  cvt_kernel<<<32, 256>>>(kv_w,  wkv, 64*128);
  cvt_kernel<<<16, 256>>>(proj_w,wp,  64*64);
  cvt_kernel<<<1024,256>>>(sr_w, wsr, 4096*64);
  cvt_kernel<<<64, 256>>>(fc1_w, w1,  64*256);
  cvt_kernel<<<64, 256>>>(fc2_w, w2,  256*64);

  dim3 lnb(32, 8);
  // 1) h = LN1(x)  (bf16)
  ln64_kernel<<<16384, lnb>>>(x, hb, ln1_g, ln1_b, MTOT);
  // 2) q = (h@q_w + q_b) * 0.125  (bf16)
  gemm_mma<64,64,64,true><<<dim3(1024,1), 256, SM_G64>>>(hb, wq, q_b, nullptr, nullptr, qb, 0.125f);
  // 3) sr conv partials
  conv_mma<<<dim3(16,8), 256>>>(hb, wsr, convp);
  // 4) xr = LN(sum partials + sr_b)  (bf16)
  srn_ln_kernel<<<256, lnb>>>(convp, sr_b, srn_g, srn_b, xrb);
  // 5) kv = xr @ kv_w + kv_b  (bf16)
  gemm_mma<64,128,128,true><<<dim3(16,1), 256, SM_G128>>>(xrb, wkv, kv_b, nullptr, nullptr, kvb, 1.0f);
  // 6) o = softmax(q k^T) v  (bf16)
  attn_mma<<<dim3(128, BB), 256, SM_ATTN>>>(qb, kvb, ob);
  // 7) x2 = x + o @ proj_w + proj_b  (fp32)
  gemm_mma<64,64,64,false><<<dim3(1024,1), 256, SM_G64>>>(ob, wp, proj_b, x, x2, nullptr, 1.0f);
  // 8) h = LN2(x2)  (bf16, reuse hb)
  ln64_kernel<<<16384, lnb>>>(x2, hb, ln2_g, ln2_b, MTOT);
  // 9) f = h @ fc1_w + fc1_b  (bf16)
  gemm_mma<64,128,256,true><<<dim3(1024,2), 256, SM_G128>>>(hb, w1, fc1_b, nullptr, nullptr, fb, 1.0f);
  // 10) g = gelu(dwconv3x3(f))  (bf16)
  dwconv_gelu<<<32768, 256>>>(fb, dw_w, gb);
  // 11) out = x2 + g @ fc2_w + fc2_b  (fp32)
  gemm_mma<256,64,64,false><<<dim3(1024,1), 256, SM_FC2>>>(gb, w2, fc2_b, x2, out, nullptr, 1.0f);
}

// round 3
// speedup vs baseline: 3.0008x; 1.1043x over previous
#include <cuda_runtime.h>
#include <cuda_bf16.h>
#include <math.h>
#include <stdint.h>

typedef __nv_bfloat16 bf16;

#define BB    8
#define NTOK  16384
#define CC    64
#define HIDD  256
#define NRTOK 256
#define MTOT  (BB*NTOK)   // 131072

// ---------------- scratch ----------------
__device__ bf16  g_hb [(size_t)MTOT*CC];      // ln1 out, then ln2 out
__device__ bf16  g_qb [(size_t)MTOT*CC];
__device__ float g_x2 [(size_t)MTOT*CC];
__device__ bf16  g_fb [(size_t)MTOT*HIDD];
__device__ float g_convp[(size_t)8*2048*CC];
__device__ bf16  g_xrb[(size_t)2048*CC];
__device__ bf16  g_kvb[(size_t)2048*2*CC];
__device__ bf16  g_wq [64*64];
__device__ bf16  g_wkv[64*128];
__device__ bf16  g_wp [64*64];
__device__ bf16  g_wsr[4096*64];
__device__ bf16  g_w1 [64*256];
__device__ bf16  g_w2 [256*64];

// ---------------- mma / ldmatrix helpers ----------------
__device__ __forceinline__ void mma_bf16(float& d0,float& d1,float& d2,float& d3,
    uint32_t a0,uint32_t a1,uint32_t a2,uint32_t a3,uint32_t b0,uint32_t b1){
  asm volatile("mma.sync.aligned.m16n8k16.row.col.f32.bf16.bf16.f32 "
    "{%0,%1,%2,%3}, {%4,%5,%6,%7}, {%8,%9}, {%0,%1,%2,%3};\n"
    : "+f"(d0),"+f"(d1),"+f"(d2),"+f"(d3)
    : "r"(a0),"r"(a1),"r"(a2),"r"(a3),"r"(b0),"r"(b1));
}
__device__ __forceinline__ void ldsm_x4(uint32_t* r, uint32_t addr){
  asm volatile("ldmatrix.sync.aligned.m8n8.x4.shared.b16 {%0,%1,%2,%3}, [%4];\n"
    : "=r"(r[0]),"=r"(r[1]),"=r"(r[2]),"=r"(r[3]) : "r"(addr));
}
__device__ __forceinline__ void ldsm_x4_t(uint32_t* r, uint32_t addr){
  asm volatile("ldmatrix.sync.aligned.m8n8.x4.trans.shared.b16 {%0,%1,%2,%3}, [%4];\n"
    : "=r"(r[0]),"=r"(r[1]),"=r"(r[2]),"=r"(r[3]) : "r"(addr));
}
__device__ __forceinline__ uint32_t pack2(float lo, float hi){
  __nv_bfloat162 v = __floats2bfloat162_rn(lo, hi);
  return reinterpret_cast<uint32_t&>(v);
}

// ---------------- all weight conversions in one kernel ----------------
struct CvtArgs {
  const float* s0; const float* s1; const float* s2;
  const float* s3; const float* s4; const float* s5;
  bf16 *d0,*d1,*d2,*d3,*d4,*d5;
};
__global__ void __launch_bounds__(256) cvt_all(CvtArgs a){
  int i = blockIdx.x*256 + threadIdx.x;          // total 311296
  if (i < 4096)                { a.d0[i] = __float2bfloat16(a.s0[i]); return; }
  if (i < 12288)               { int j=i-4096;   a.d1[j] = __float2bfloat16(a.s1[j]); return; }
  if (i < 16384)               { int j=i-12288;  a.d2[j] = __float2bfloat16(a.s2[j]); return; }
  if (i < 278528)              { int j=i-16384;  a.d3[j] = __float2bfloat16(a.s3[j]); return; }
  if (i < 294912)              { int j=i-278528; a.d4[j] = __float2bfloat16(a.s4[j]); return; }
  if (i < 311296)              { int j=i-294912; a.d5[j] = __float2bfloat16(a.s5[j]); return; }
}

// ---------------- fused LN1 + q-GEMM (writes h bf16 and q bf16) ----------------
__global__ void __launch_bounds__(256) ln1q_kernel(
    const float* __restrict__ x, const bf16* __restrict__ wq,
    const float* __restrict__ qbias, const float* __restrict__ g1,
    const float* __restrict__ b1, bf16* __restrict__ hb, bf16* __restrict__ qb)
{
  __shared__ bf16 Ws[64*72];
  __shared__ bf16 As[128*72];
  int t = threadIdx.x, w = t>>5, lane = t&31;
  size_t rowbase = (size_t)blockIdx.x * 128;

  for (int i = t; i < 512; i += 256){
    int row = i>>3, c8 = i&7;
    *(float4*)(Ws + row*72 + c8*8) = *(const float4*)(wq + row*64 + c8*8);
  }

  // LN: each thread owns half a row (32 cols)
  {
    int r = t>>1, half = t&1, col0 = half*32;
    const float* xr = x + (rowbase + r)*64 + col0;
    float v[32];
    #pragma unroll
    for (int j = 0; j < 8; j++) *(float4*)(v + j*4) = *(const float4*)(xr + j*4);
    float s = 0.f;
    #pragma unroll
    for (int j = 0; j < 32; j++) s += v[j];
    s += __shfl_xor_sync(0xffffffffu, s, 1);
    float mean = s * (1.0f/64.0f);
    float qv = 0.f;
    #pragma unroll
    for (int j = 0; j < 32; j++){ float d = v[j]-mean; qv += d*d; }
    qv += __shfl_xor_sync(0xffffffffu, qv, 1);
    float rstd = rsqrtf(qv*(1.0f/64.0f) + 1e-5f);
    #pragma unroll
    for (int j = 0; j < 16; j++){
      int c = col0 + 2*j;
      float2 gg = *(const float2*)(g1 + c);
      float2 bb = *(const float2*)(b1 + c);
      uint32_t u = pack2((v[2*j]-mean)*rstd*gg.x + bb.x,
                         (v[2*j+1]-mean)*rstd*gg.y + bb.y);
      *(uint32_t*)(As + r*72 + c) = u;
      *(uint32_t*)(hb + (rowbase + r)*64 + c) = u;
    }
  }
  __syncthreads();

  float acc[8][4];
  #pragma unroll
  for (int nb = 0; nb < 8; nb++){ acc[nb][0]=acc[nb][1]=acc[nb][2]=acc[nb][3]=0.f; }
  uint32_t As_u = (uint32_t)__cvta_generic_to_shared(As);
  uint32_t Ws_u = (uint32_t)__cvta_generic_to_shared(Ws);
  uint32_t a_base = As_u + ((w*16 + (lane&15))*72 + (lane>>4)*8)*2;
  uint32_t b_off  = (lane&15)*144 + (lane>>4)*16;
  #pragma unroll
  for (int kb = 0; kb < 4; kb++){
    uint32_t a[4];
    ldsm_x4(a, a_base + kb*32);
    uint32_t brow = Ws_u + (uint32_t)(kb*16)*144 + b_off;
    #pragma unroll
    for (int n2 = 0; n2 < 4; n2++){
      uint32_t b[4];
      ldsm_x4_t(b, brow + n2*32);
      mma_bf16(acc[2*n2  ][0],acc[2*n2  ][1],acc[2*n2  ][2],acc[2*n2  ][3],
               a[0],a[1],a[2],a[3], b[0],b[1]);
      mma_bf16(acc[2*n2+1][0],acc[2*n2+1][1],acc[2*n2+1][2],acc[2*n2+1][3],
               a[0],a[1],a[2],a[3], b[2],b[3]);
    }
  }
  int g = lane>>2, tq = lane&3;
  size_t r0 = rowbase + w*16 + g, r1 = r0 + 8;
  #pragma unroll
  for (int nb = 0; nb < 8; nb++){
    int col = nb*8 + tq*2;
    float b0 = qbias[col], b1v = qbias[col+1];
    *(uint32_t*)(qb + r0*64 + col) = pack2((acc[nb][0]+b0)*0.125f, (acc[nb][1]+b1v)*0.125f);
    *(uint32_t*)(qb + r1*64 + col) = pack2((acc[nb][2]+b0)*0.125f, (acc[nb][3]+b1v)*0.125f);
  }
}

// ---------------- generic bf16 GEMM (kv + fc1) ----------------
template<int KD, int ND, int NSRC>
__global__ void __launch_bounds__(256) gemm_mma(
    const bf16* __restrict__ A, const bf16* __restrict__ W,
    const float* __restrict__ bias, bf16* __restrict__ outB)
{
  constexpr int WSTR = ND + 8;
  extern __shared__ bf16 smg[];
  bf16* Ws = smg;
  bf16* As = smg + KD*WSTR;
  int t = threadIdx.x, w = t>>5, lane = t&31;
  int col0 = blockIdx.y * ND;
  size_t rowbase = (size_t)blockIdx.x * 128;

  for (int i = t; i < KD*(ND/8); i += 256){
    int row = i/(ND/8), c8 = i%(ND/8);
    *(float4*)(Ws + row*WSTR + c8*8) = *(const float4*)(W + (size_t)row*NSRC + col0 + c8*8);
  }
  float acc[ND/8][4];
  #pragma unroll
  for (int nb = 0; nb < ND/8; nb++){ acc[nb][0]=acc[nb][1]=acc[nb][2]=acc[nb][3]=0.f; }
  uint32_t As_u = (uint32_t)__cvta_generic_to_shared(As);
  uint32_t Ws_u = (uint32_t)__cvta_generic_to_shared(Ws);
  uint32_t a_base = As_u + ((w*16 + (lane&15))*72 + (lane>>4)*8)*2;
  uint32_t b_off  = (lane&15)*WSTR*2 + (lane>>4)*16;

  for (int kc = 0; kc < KD; kc += 64){
    __syncthreads();
    for (int i = t; i < 1024; i += 256){
      int r = i>>3, c8 = i&7;
      *(float4*)(As + r*72 + c8*8) = *(const float4*)(A + (rowbase + r)*KD + kc + c8*8);
    }
    __syncthreads();
    #pragma unroll
    for (int kb = 0; kb < 4; kb++){
      uint32_t a[4];
      ldsm_x4(a, a_base + kb*32);
      uint32_t brow = Ws_u + (uint32_t)(kc + kb*16)*WSTR*2 + b_off;
      #pragma unroll
      for (int n2 = 0; n2 < ND/16; n2++){
        uint32_t b[4];
        ldsm_x4_t(b, brow + n2*32);
        mma_bf16(acc[2*n2  ][0],acc[2*n2  ][1],acc[2*n2  ][2],acc[2*n2  ][3],
                 a[0],a[1],a[2],a[3], b[0],b[1]);
        mma_bf16(acc[2*n2+1][0],acc[2*n2+1][1],acc[2*n2+1][2],acc[2*n2+1][3],
                 a[0],a[1],a[2],a[3], b[2],b[3]);
      }
    }
  }
  int g = lane>>2, tq = lane&3;
  size_t r0 = rowbase + w*16 + g, r1 = r0 + 8;
  #pragma unroll
  for (int nb = 0; nb < ND/8; nb++){
    int col = col0 + nb*8 + tq*2;
    float b0 = bias[col], b1 = bias[col+1];
    *(uint32_t*)(outB + r0*NSRC + col) = pack2(acc[nb][0]+b0, acc[nb][1]+b1);
    *(uint32_t*)(outB + r1*NSRC + col) = pack2(acc[nb][2]+b0, acc[nb][3]+b1);
  }
}

// ---------------- sr conv (split-K mma) ----------------
__global__ void __launch_bounds__(256) conv_mma(
    const bf16* __restrict__ h, const bf16* __restrict__ wsr,
    float* __restrict__ part)
{
  __shared__ bf16 Ws[64*72];
  __shared__ bf16 As[128*72];
  int t = threadIdx.x, w = t>>5, lane = t&31;
  int r1 = blockIdx.y;
  int pbase = blockIdx.x * 128;

  float acc[8][4];
  #pragma unroll
  for (int nb = 0; nb < 8; nb++){ acc[nb][0]=acc[nb][1]=acc[nb][2]=acc[nb][3]=0.f; }
  uint32_t As_u = (uint32_t)__cvta_generic_to_shared(As);
  uint32_t Ws_u = (uint32_t)__cvta_generic_to_shared(Ws);
  uint32_t a_base = As_u + ((w*16 + (lane&15))*72 + (lane>>4)*8)*2;
  uint32_t b_off  = (lane&15)*144 + (lane>>4)*16;

  for (int kk = 0; kk < 8; kk++){
    __syncthreads();
    for (int i = t; i < 512; i += 256){
      int row = i>>3, c8 = i&7;
      *(float4*)(Ws + row*72 + c8*8) =
        *(const float4*)(wsr + ((size_t)(r1*512 + kk*64 + row))*64 + c8*8);
    }
    for (int i = t; i < 1024; i += 256){
      int r = i>>3, c8 = i&7;
      int p = pbase + r;
      int b = p>>8, ph = (p>>4)&15, pw = p&15;
      size_t src = ((((size_t)b*128 + ph*8 + r1)*128) + pw*8)*64 + kk*64 + c8*8;
      *(float4*)(As + r*72 + c8*8) = *(const float4*)(h + src);
    }
    __syncthreads();
    #pragma unroll
    for (int kb = 0; kb < 4; kb++){
      uint32_t a[4];
      ldsm_x4(a, a_base + kb*32);
      uint32_t brow = Ws_u + (uint32_t)(kb*16)*144 + b_off;
      #pragma unroll
      for (int n2 = 0; n2 < 4; n2++){
        uint32_t b[4];
        ldsm_x4_t(b, brow + n2*32);
        mma_bf16(acc[2*n2  ][0],acc[2*n2  ][1],acc[2*n2  ][2],acc[2*n2  ][3],
                 a[0],a[1],a[2],a[3], b[0],b[1]);
        mma_bf16(acc[2*n2+1][0],acc[2*n2+1][1],acc[2*n2+1][2],acc[2*n2+1][3],
                 a[0],a[1],a[2],a[3], b[2],b[3]);
      }
    }
  }
  int g = lane>>2, tq = lane&3;
  size_t p0 = pbase + w*16 + g, p1 = p0 + 8;
  #pragma unroll
  for (int nb = 0; nb < 8; nb++){
    int col = nb*8 + tq*2;
    *(float2*)(part + ((size_t)r1*2048 + p0)*64 + col) = make_float2(acc[nb][0], acc[nb][1]);
    *(float2*)(part + ((size_t)r1*2048 + p1)*64 + col) = make_float2(acc[nb][2], acc[nb][3]);
  }
}

// ---------------- srn reduce + LN ----------------
__global__ void __launch_bounds__(256) srn_ln_kernel(
    const float* __restrict__ part, const float* __restrict__ srb,
    const float* __restrict__ gamma, const float* __restrict__ beta,
    bf16* __restrict__ out)
{
  int row = blockIdx.x*8 + threadIdx.y;
  int lane = threadIdx.x;
  float2 v = make_float2(0.f, 0.f);
  #pragma unroll
  for (int s = 0; s < 8; s++){
    float2 p = ((const float2*)(part + ((size_t)s*2048 + row)*64))[lane];
    v.x += p.x; v.y += p.y;
  }
  float2 sb = ((const float2*)srb)[lane];
  v.x += sb.x; v.y += sb.y;
  float s = v.x + v.y;
  #pragma unroll
  for (int o = 16; o; o >>= 1) s += __shfl_xor_sync(0xffffffffu, s, o);
  float mean = s * (1.0f/64.0f);
  float dx = v.x - mean, dy = v.y - mean;
  float vs = dx*dx + dy*dy;
  #pragma unroll
  for (int o = 16; o; o >>= 1) vs += __shfl_xor_sync(0xffffffffu, vs, o);
  float rstd = rsqrtf(vs*(1.0f/64.0f) + 1e-5f);
  float2 gg = ((const float2*)gamma)[lane];
  float2 bb = ((const float2*)beta)[lane];
  ((uint32_t*)(out + (size_t)row*64))[lane] =
      pack2(dx*rstd*gg.x + bb.x, dy*rstd*gg.y + bb.y);
}

// ---------------- attention + proj + residual + LN2 (all fused) ----------------
__global__ void __launch_bounds__(256) attn_proj_ln(
    const bf16* __restrict__ q, const bf16* __restrict__ kv,
    const bf16* __restrict__ wp, const float* __restrict__ pbias,
    const float* __restrict__ x, const float* __restrict__ g2,
    const float* __restrict__ b2, float* __restrict__ x2, bf16* __restrict__ hb2)
{
  extern __shared__ bf16 sma[];
  bf16* Qs = sma;              // 128 x 72
  bf16* Ks = sma + 128*72;     // 256 x 72
  bf16* Vs = Ks  + 256*72;     // 256 x 72
  bf16* Ps = Vs  + 256*72;     // 64 x 72 (proj weight)
  int t = threadIdx.x, w = t>>5, lane = t&31;
  int b = blockIdx.y;
  size_t qrow0 = (size_t)b*NTOK + (size_t)blockIdx.x*128;
  const bf16* kvb = kv + (size_t)b*NRTOK*128;

  for (int i = t; i < 1024; i += 256){
    int r = i>>3, c8 = i&7;
    *(float4*)(Qs + r*72 + c8*8) = *(const float4*)(q + (qrow0 + r)*64 + c8*8);
  }
  for (int i = t; i < 2048; i += 256){
    int r = i>>3, c8 = i&7;
    *(float4*)(Ks + r*72 + c8*8) = *(const float4*)(kvb + (size_t)r*128 + c8*8);
  }
  for (int i = t; i < 2048; i += 256){
    int r = i>>3, c8 = i&7;
    *(float4*)(Vs + r*72 + c8*8) = *(const float4*)(kvb + (size_t)r*128 + 64 + c8*8);
  }
  for (int i = t; i < 512; i += 256){
    int r = i>>3, c8 = i&7;
    *(float4*)(Ps + r*72 + c8*8) = *(const float4*)(wp + r*64 + c8*8);
  }
  __syncthreads();

  uint32_t Qs_u = (uint32_t)__cvta_generic_to_shared(Qs);
  uint32_t Ks_u = (uint32_t)__cvta_generic_to_shared(Ks);
  uint32_t Vs_u = (uint32_t)__cvta_generic_to_shared(Vs);
  uint32_t Ps_u = (uint32_t)__cvta_generic_to_shared(Ps);
  uint32_t a_base = Qs_u + ((w*16 + (lane&15))*72 + (lane>>4)*8)*2;
  uint32_t k_off = ((((lane>>4)&1)*8 + (lane&7)))*144 + ((lane>>3)&1)*16;
  uint32_t v_off = (lane&15)*144 + (lane>>4)*16;

  float s[32][4];
  #pragma unroll
  for (int nb = 0; nb < 32; nb++){ s[nb][0]=s[nb][1]=s[nb][2]=s[nb][3]=0.f; }

  #pragma unroll
  for (int kb = 0; kb < 4; kb++){
    uint32_t a[4];
    ldsm_x4(a, a_base + kb*32);
    #pragma unroll
    for (int ng = 0; ng < 16; ng++){
      uint32_t bb[4];
      ldsm_x4(bb, Ks_u + (uint32_t)ng*2304 + kb*32 + k_off);
      mma_bf16(s[2*ng  ][0],s[2*ng  ][1],s[2*ng  ][2],s[2*ng  ][3],
               a[0],a[1],a[2],a[3], bb[0],bb[1]);
      mma_bf16(s[2*ng+1][0],s[2*ng+1][1],s[2*ng+1][2],s[2*ng+1][3],
               a[0],a[1],a[2],a[3], bb[2],bb[3]);
    }
  }

  // softmax over 256 keys
  float mx0 = -1e30f, mx1 = -1e30f;
  #pragma unroll
  for (int nb = 0; nb < 32; nb++){
    mx0 = fmaxf(mx0, fmaxf(s[nb][0], s[nb][1]));
    mx1 = fmaxf(mx1, fmaxf(s[nb][2], s[nb][3]));
  }
  mx0 = fmaxf(mx0, __shfl_xor_sync(0xffffffffu, mx0, 1));
  mx0 = fmaxf(mx0, __shfl_xor_sync(0xffffffffu, mx0, 2));
  mx1 = fmaxf(mx1, __shfl_xor_sync(0xffffffffu, mx1, 1));
  mx1 = fmaxf(mx1, __shfl_xor_sync(0xffffffffu, mx1, 2));
  float sm0 = 0.f, sm1 = 0.f;
  #pragma unroll
  for (int nb = 0; nb < 32; nb++){
    s[nb][0] = __expf(s[nb][0] - mx0); sm0 += s[nb][0];
    s[nb][1] = __expf(s[nb][1] - mx0); sm0 += s[nb][1];
    s[nb][2] = __expf(s[nb][2] - mx1); sm1 += s[nb][2];
    s[nb][3] = __expf(s[nb][3] - mx1); sm1 += s[nb][3];
  }
  sm0 += __shfl_xor_sync(0xffffffffu, sm0, 1);
  sm0 += __shfl_xor_sync(0xffffffffu, sm0, 2);
  sm1 += __shfl_xor_sync(0xffffffffu, sm1, 1);
  sm1 += __shfl_xor_sync(0xffffffffu, sm1, 2);
  float inv0 = __frcp_rn(sm0), inv1 = __frcp_rn(sm1);
  #pragma unroll
  for (int nb = 0; nb < 32; nb++){
    s[nb][0] *= inv0; s[nb][1] *= inv0; s[nb][2] *= inv1; s[nb][3] *= inv1;
  }

  // O = P @ V
  float oo[8][4];
  #pragma unroll
  for (int nb = 0; nb < 8; nb++){ oo[nb][0]=oo[nb][1]=oo[nb][2]=oo[nb][3]=0.f; }
  #pragma unroll
  for (int kb = 0; kb < 16; kb++){
    uint32_t a0 = pack2(s[2*kb  ][0], s[2*kb  ][1]);
    uint32_t a1 = pack2(s[2*kb  ][2], s[2*kb  ][3]);
    uint32_t a2 = pack2(s[2*kb+1][0], s[2*kb+1][1]);
    uint32_t a3 = pack2(s[2*kb+1][2], s[2*kb+1][3]);
    uint32_t base = Vs_u + (uint32_t)kb*16*144 + v_off;
    #pragma unroll
    for (int n2 = 0; n2 < 4; n2++){
      uint32_t bb[4];
      ldsm_x4_t(bb, base + n2*32);
      mma_bf16(oo[2*n2  ][0],oo[2*n2  ][1],oo[2*n2  ][2],oo[2*n2  ][3],
               a0,a1,a2,a3, bb[0],bb[1]);
      mma_bf16(oo[2*n2+1][0],oo[2*n2+1][1],oo[2*n2+1][2],oo[2*n2+1][3],
               a0,a1,a2,a3, bb[2],bb[3]);
    }
  }

  // proj GEMM: o (c-frag -> a-frag) @ wp
  float acc2[8][4];
  #pragma unroll
  for (int nb = 0; nb < 8; nb++){ acc2[nb][0]=acc2[nb][1]=acc2[nb][2]=acc2[nb][3]=0.f; }
  #pragma unroll
  for (int kb = 0; kb < 4; kb++){
    uint32_t a0 = pack2(oo[2*kb  ][0], oo[2*kb  ][1]);
    uint32_t a1 = pack2(oo[2*kb  ][2], oo[2*kb  ][3]);
    uint32_t a2 = pack2(oo[2*kb+1][0], oo[2*kb+1][1]);
    uint32_t a3 = pack2(oo[2*kb+1][2], oo[2*kb+1][3]);
    uint32_t brow = Ps_u + (uint32_t)kb*16*144 + v_off;
    #pragma unroll
    for (int n2 = 0; n2 < 4; n2++){
      uint32_t bb[4];
      ldsm_x4_t(bb, brow + n2*32);
      mma_bf16(acc2[2*n2  ][0],acc2[2*n2  ][1],acc2[2*n2  ][2],acc2[2*n2  ][3],
               a0,a1,a2,a3, bb[0],bb[1]);
      mma_bf16(acc2[2*n2+1][0],acc2[2*n2+1][1],acc2[2*n2+1][2],acc2[2*n2+1][3],
               a0,a1,a2,a3, bb[2],bb[3]);
    }
  }

  // epilogue: x2 = x + proj; hb2 = LN2(x2)
  int g = lane>>2, tq = lane&3;
  size_t r0 = qrow0 + w*16 + g, r1 = r0 + 8;
  float v0[16], v1[16];
  float s0 = 0.f, s1 = 0.f;
  #pragma unroll
  for (int nb = 0; nb < 8; nb++){
    int col = nb*8 + tq*2;
    float pb0 = pbias[col], pb1 = pbias[col+1];
    float2 xx0 = *(const float2*)(x + r0*64 + col);
    float2 xx1 = *(const float2*)(x + r1*64 + col);
    v0[2*nb]   = acc2[nb][0] + pb0 + xx0.x;
    v0[2*nb+1] = acc2[nb][1] + pb1 + xx0.y;
    v1[2*nb]   = acc2[nb][2] + pb0 + xx1.x;
    v1[2*nb+1] = acc2[nb][3] + pb1 + xx1.y;
    s0 += v0[2*nb] + v0[2*nb+1];
    s1 += v1[2*nb] + v1[2*nb+1];
  }
  s0 += __shfl_xor_sync(0xffffffffu, s0, 1);
  s0 += __shfl_xor_sync(0xffffffffu, s0, 2);
  s1 += __shfl_xor_sync(0xffffffffu, s1, 1);
  s1 += __shfl_xor_sync(0xffffffffu, s1, 2);
  float m0 = s0*(1.0f/64.0f), m1 = s1*(1.0f/64.0f);
  float q0 = 0.f, q1 = 0.f;
  #pragma unroll
  for (int j = 0; j < 16; j++){
    float d0 = v0[j]-m0, d1 = v1[j]-m1;
    q0 += d0*d0; q1 += d1*d1;
  }
  q0 += __shfl_xor_sync(0xffffffffu, q0, 1);
  q0 += __shfl_xor_sync(0xffffffffu, q0, 2);
  q1 += __shfl_xor_sync(0xffffffffu, q1, 1);
  q1 += __shfl_xor_sync(0xffffffffu, q1, 2);
  float rs0 = rsqrtf(q0*(1.0f/64.0f) + 1e-5f);
  float rs1 = rsqrtf(q1*(1.0f/64.0f) + 1e-5f);
  #pragma unroll
  for (int nb = 0; nb < 8; nb++){
    int col = nb*8 + tq*2;
    *(float2*)(x2 + r0*64 + col) = make_float2(v0[2*nb], v0[2*nb+1]);
    *(float2*)(x2 + r1*64 + col) = make_float2(v1[2*nb], v1[2*nb+1]);
    float2 gg = *(const float2*)(g2 + col);
    float2 bb = *(const float2*)(b2 + col);
    *(uint32_t*)(hb2 + r0*64 + col) =
        pack2((v0[2*nb]-m0)*rs0*gg.x + bb.x, (v0[2*nb+1]-m0)*rs0*gg.y + bb.y);
    *(uint32_t*)(hb2 + r1*64 + col) =
        pack2((v1[2*nb]-m1)*rs1*gg.x + bb.x, (v1[2*nb+1]-m1)*rs1*gg.y + bb.y);
  }
}

// ---------------- fused dwconv3x3 + GELU + fc2 + residual ----------------
__global__ void __launch_bounds__(256) fc2_fused(
    const bf16* __restrict__ f, const float* __restrict__ dw,
    const bf16* __restrict__ w2, const float* __restrict__ bias2,
    const float* __restrict__ x2, float* __restrict__ out)
{
  extern __shared__ bf16 smf[];
  bf16* Ws = smf;                 // 256 x 72
  bf16* Fs = smf + 256*72;        // 3 x 128 x 72
  bf16* Gs = Fs  + 3*128*72;      // 128 x 72
  int t = threadIdx.x, w = t>>5, lane = t&31;
  int by = blockIdx.x;
  int b = by >> 7, y = by & 127;
  size_t tokbase = (size_t)b*NTOK + (size_t)y*128;

  for (int i = t; i < 2048; i += 256){
    int row = i>>3, c8 = i&7;
    *(float4*)(Ws + row*72 + c8*8) = *(const float4*)(w2 + row*64 + c8*8);
  }

  float acc[8][4];
  #pragma unroll
  for (int nb = 0; nb < 8; nb++){ acc[nb][0]=acc[nb][1]=acc[nb][2]=acc[nb][3]=0.f; }
  uint32_t Ws_u = (uint32_t)__cvta_generic_to_shared(Ws);
  uint32_t Gs_u = (uint32_t)__cvta_generic_to_shared(Gs);
  uint32_t a_base = Gs_u + ((w*16 + (lane&15))*72 + (lane>>4)*8)*2;
  uint32_t b_off  = (lane&15)*144 + (lane>>4)*16;

  int chl = (lane)*2;          // channel pair within chunk (0..62)
  int px0 = w*16;              // warp w handles pixels w*16..w*16+15

  for (int kc = 0; kc < 256; kc += 64){
    __syncthreads();
    // stage 3 rows of f for this channel chunk
    for (int i = t; i < 3072; i += 256){
      int row3 = i>>10, rem = i&1023, px = rem>>3, c8 = rem&7;
      int yy = y + row3 - 1;
      float4 val;
      if (yy >= 0 && yy < 128)
        val = *(const float4*)(f + ((size_t)b*NTOK + (size_t)yy*128 + px)*256 + kc + c8*8);
      else
        val = make_float4(0.f,0.f,0.f,0.f);
      *(float4*)(Fs + row3*9216 + px*72 + c8*8) = val;
    }
    __syncthreads();

    // dwconv 3x3 + gelu -> Gs (sliding window along x, 2 channels per lane)
    {
      float w9[2][9];
      #pragma unroll
      for (int i = 0; i < 9; i++){
        float2 wv = *(const float2*)(dw + i*256 + kc + chl);
        w9[0][i] = wv.x; w9[1][i] = wv.y;
      }
      uint32_t colv[3][3];   // [xoff][dy], each = 2 packed bf16 channels
      #pragma unroll
      for (int dy = 0; dy < 3; dy++){
        colv[0][dy] = (px0 > 0) ? *(uint32_t*)(Fs + dy*9216 + (px0-1)*72 + chl) : 0u;
        colv[1][dy] = *(uint32_t*)(Fs + dy*9216 + px0*72 + chl);
      }
      #pragma unroll
      for (int pi = 0; pi < 16; pi++){
        int px = px0 + pi;
        #pragma unroll
        for (int dy = 0; dy < 3; dy++)
          colv[2][dy] = (px+1 < 128) ? *(uint32_t*)(Fs + dy*9216 + (px+1)*72 + chl) : 0u;
        float a0 = 0.f, a1 = 0.f;
        #pragma unroll
        for (int dy = 0; dy < 3; dy++)
          #pragma unroll
          for (int dx = 0; dx < 3; dx++){
            float2 vv = __bfloat1622float2(
                *reinterpret_cast<const __nv_bfloat162*>(&colv[dx][dy]));
            a0 = fmaf(vv.x, w9[0][dy*3+dx], a0);
            a1 = fmaf(vv.y, w9[1][dy*3+dx], a1);
          }
        a0 = 0.5f*a0*(1.0f + erff(a0*0.70710678118654752f));
        a1 = 0.5f*a1*(1.0f + erff(a1*0.70710678118654752f));
        *(uint32_t*)(Gs + px*72 + chl) = pack2(a0, a1);
        #pragma unroll
        for (int dy = 0; dy < 3; dy++){ colv[0][dy] = colv[1][dy]; colv[1][dy] = colv[2][dy]; }
      }
    }
    __syncwarp();

    // accumulate Gs @ Ws[kc..kc+64)
    #pragma unroll
    for (int kb = 0; kb < 4; kb++){
      uint32_t a[4];
      ldsm_x4(a, a_base + kb*32);
      uint32_t brow = Ws_u + (uint32_t)(kc + kb*16)*144 + b_off;
      #pragma unroll
      for (int n2 = 0; n2 < 4; n2++){
        uint32_t bb[4];
        ldsm_x4_t(bb, brow + n2*32);
        mma_bf16(acc[2*n2  ][0],acc[2*n2  ][1],acc[2*n2  ][2],acc[2*n2  ][3],
                 a[0],a[1],a[2],a[3], bb[0],bb[1]);
        mma_bf16(acc[2*n2+1][0],acc[2*n2+1][1],acc[2*n2+1][2],acc[2*n2+1][3],
                 a[0],a[1],a[2],a[3], bb[2],bb[3]);
      }
    }
  }

  int g = lane>>2, tq = lane&3;
  size_t r0 = tokbase + w*16 + g, r1 = r0 + 8;
  #pragma unroll
  for (int nb = 0; nb < 8; nb++){
    int col = nb*8 + tq*2;
    float b0 = bias2[col], b1 = bias2[col+1];
    float2 q0 = *(const float2*)(x2 + r0*64 + col);
    float2 q1 = *(const float2*)(x2 + r1*64 + col);
    *(float2*)(out + r0*64 + col) = make_float2(acc[nb][0]+b0+q0.x, acc[nb][1]+b1+q0.y);
    *(float2*)(out + r1*64 + col) = make_float2(acc[nb][2]+b0+q1.x, acc[nb][3]+b1+q1.y);
  }
}

// ---------------- launch ----------------
extern "C" void kernel_launch(void* const* d_in, const int* in_sizes, int n_in,
                              void* d_out, int out_size)
{
  const float* x      = (const float*)d_in[0];
  const float* ln1_g  = (const float*)d_in[3];
  const float* ln1_b  = (const float*)d_in[4];
  const float* q_w    = (const float*)d_in[5];
  const float* q_b    = (const float*)d_in[6];
  const float* kv_w   = (const float*)d_in[7];
  const float* kv_b   = (const float*)d_in[8];
  const float* proj_w = (const float*)d_in[9];
  const float* proj_b = (const float*)d_in[10];
  const float* sr_w   = (const float*)d_in[11];
  const float* sr_b   = (const float*)d_in[12];
  const float* srn_g  = (const float*)d_in[13];
  const float* srn_b  = (const float*)d_in[14];
  const float* ln2_g  = (const float*)d_in[15];
  const float* ln2_b  = (const float*)d_in[16];
  const float* fc1_w  = (const float*)d_in[17];
  const float* fc1_b  = (const float*)d_in[18];
  const float* dw_w   = (const float*)d_in[19];
  const float* fc2_w  = (const float*)d_in[20];
  const float* fc2_b  = (const float*)d_in[21];
  float* out = (float*)d_out;

  bf16 *hb,*qb,*fb,*xrb,*kvb,*wq,*wkv,*wp,*wsr,*w1,*w2;
  float *x2,*convp;
  cudaGetSymbolAddress((void**)&hb,  g_hb);
  cudaGetSymbolAddress((void**)&qb,  g_qb);
  cudaGetSymbolAddress((void**)&x2,  g_x2);
  cudaGetSymbolAddress((void**)&fb,  g_fb);
  cudaGetSymbolAddress((void**)&convp, g_convp);
  cudaGetSymbolAddress((void**)&xrb, g_xrb);
  cudaGetSymbolAddress((void**)&kvb, g_kvb);
  cudaGetSymbolAddress((void**)&wq,  g_wq);
  cudaGetSymbolAddress((void**)&wkv, g_wkv);
  cudaGetSymbolAddress((void**)&wp,  g_wp);
  cudaGetSymbolAddress((void**)&wsr, g_wsr);
  cudaGetSymbolAddress((void**)&w1,  g_w1);
  cudaGetSymbolAddress((void**)&w2,  g_w2);

  const int SM_G128 = (64*136 + 128*72)*2;            // kv + fc1 dynamic smem
  const int SM_ATTN = (128 + 256 + 256 + 64)*72*2;    // 101376
  const int SM_FC2  = (256 + 3*128 + 128)*72*2;       // 110592

  cudaFuncSetAttribute((const void*)gemm_mma<64,128,128>,
                       cudaFuncAttributeMaxDynamicSharedMemorySize, SM_G128);
  cudaFuncSetAttribute((const void*)gemm_mma<64,128,256>,
                       cudaFuncAttributeMaxDynamicSharedMemorySize, SM_G128);
  cudaFuncSetAttribute((const void*)attn_proj_ln,
                       cudaFuncAttributeMaxDynamicSharedMemorySize, SM_ATTN);
  cudaFuncSetAttribute((const void*)fc2_fused,
                       cudaFuncAttributeMaxDynamicSharedMemorySize, SM_FC2);

  // 1) all weight conversions
  CvtArgs ca = { q_w, kv_w, proj_w, sr_w, fc1_w, fc2_w, wq, wkv, wp, wsr, w1, w2 };
  cvt_all<<<1216, 256>>>(ca);
  // 2) h = LN1(x); q = (h@q_w + q_b)*0.125
  ln1q_kernel<<<1024, 256>>>(x, wq, q_b, ln1_g, ln1_b, hb, qb);
  // 3) sr conv partials
  conv_mma<<<dim3(16,8), 256>>>(hb, wsr, convp);
  // 4) xr = LN(sum partials + sr_b)
  srn_ln_kernel<<<256, dim3(32,8)>>>(convp, sr_b, srn_g, srn_b, xrb);
  // 5) kv = xr @ kv_w + kv_b
  gemm_mma<64,128,128><<<dim3(16,1), 256, SM_G128>>>(xrb, wkv, kv_b, kvb);
  // 6) x2 = x + softmax(qk^T)v @ proj_w + proj_b ; hb = LN2(x2)
  attn_proj_ln<<<dim3(128, BB), 256, SM_ATTN>>>(qb, kvb, wp, proj_b, x,
                                                ln2_g, ln2_b, x2, hb);
  // 7) f = hb @ fc1_w + fc1_b
  gemm_mma<64,128,256><<<dim3(1024,2), 256, SM_G128>>>(hb, w1, fc1_b, fb);
  // 8) out = x2 + gelu(dwconv(f)) @ fc2_w + fc2_b
  fc2_fused<<<1024, 256, SM_FC2>>>(fb, dw_w, w2, fc2_b, x2, out);
}

// round 4
// speedup vs baseline: 3.0168x; 1.0053x over previous
#include <cuda_runtime.h>
#include <cuda_bf16.h>
#include <math.h>
#include <stdint.h>

typedef __nv_bfloat16 bf16;

#define BB    8
#define NTOK  16384
#define CC    64
#define HIDD  256
#define NRTOK 256
#define MTOT  (BB*NTOK)   // 131072

// ---------------- scratch ----------------
__device__ bf16  g_hb [(size_t)MTOT*CC];      // ln1 out
__device__ bf16  g_qb [(size_t)MTOT*CC];
__device__ float g_x2 [(size_t)MTOT*CC];
__device__ bf16  g_fb [(size_t)MTOT*HIDD];
__device__ float g_convp[(size_t)8*2048*CC];
__device__ bf16  g_kvb[(size_t)2048*2*CC];
__device__ bf16  g_wq [64*64];
__device__ bf16  g_wkv[64*128];
__device__ bf16  g_wp [64*64];
__device__ bf16  g_wsr[4096*64];
__device__ bf16  g_w1 [64*256];
__device__ bf16  g_w2 [256*64];

// ---------------- mma / ldmatrix / cp.async helpers ----------------
__device__ __forceinline__ void mma_bf16(float& d0,float& d1,float& d2,float& d3,
    uint32_t a0,uint32_t a1,uint32_t a2,uint32_t a3,uint32_t b0,uint32_t b1){
  asm volatile("mma.sync.aligned.m16n8k16.row.col.f32.bf16.bf16.f32 "
    "{%0,%1,%2,%3}, {%4,%5,%6,%7}, {%8,%9}, {%0,%1,%2,%3};\n"
    : "+f"(d0),"+f"(d1),"+f"(d2),"+f"(d3)
    : "r"(a0),"r"(a1),"r"(a2),"r"(a3),"r"(b0),"r"(b1));
}
__device__ __forceinline__ void ldsm_x4(uint32_t* r, uint32_t addr){
  asm volatile("ldmatrix.sync.aligned.m8n8.x4.shared.b16 {%0,%1,%2,%3}, [%4];\n"
    : "=r"(r[0]),"=r"(r[1]),"=r"(r[2]),"=r"(r[3]) : "r"(addr));
}
__device__ __forceinline__ void ldsm_x4_t(uint32_t* r, uint32_t addr){
  asm volatile("ldmatrix.sync.aligned.m8n8.x4.trans.shared.b16 {%0,%1,%2,%3}, [%4];\n"
    : "=r"(r[0]),"=r"(r[1]),"=r"(r[2]),"=r"(r[3]) : "r"(addr));
}
__device__ __forceinline__ uint32_t pack2(float lo, float hi){
  __nv_bfloat162 v = __floats2bfloat162_rn(lo, hi);
  return reinterpret_cast<uint32_t&>(v);
}
__device__ __forceinline__ void cp_async16(uint32_t saddr, const void* gptr){
  asm volatile("cp.async.ca.shared.global [%0], [%1], 16;\n" :: "r"(saddr), "l"(gptr));
}
__device__ __forceinline__ void cp_async_commit(){ asm volatile("cp.async.commit_group;\n"); }
__device__ __forceinline__ void cp_async_wait0(){ asm volatile("cp.async.wait_group 0;\n"); }

// ---------------- all weight conversions in one kernel ----------------
struct CvtArgs {
  const float* s0; const float* s1; const float* s2;
  const float* s3; const float* s4; const float* s5;
  bf16 *d0,*d1,*d2,*d3,*d4,*d5;
};
__global__ void __launch_bounds__(256) cvt_all(CvtArgs a){
  int i = blockIdx.x*256 + threadIdx.x;          // total 311296
  if (i < 4096)                { a.d0[i] = __float2bfloat16(a.s0[i]); return; }
  if (i < 12288)               { int j=i-4096;   a.d1[j] = __float2bfloat16(a.s1[j]); return; }
  if (i < 16384)               { int j=i-12288;  a.d2[j] = __float2bfloat16(a.s2[j]); return; }
  if (i < 278528)              { int j=i-16384;  a.d3[j] = __float2bfloat16(a.s3[j]); return; }
  if (i < 294912)              { int j=i-278528; a.d4[j] = __float2bfloat16(a.s4[j]); return; }
  if (i < 311296)              { int j=i-294912; a.d5[j] = __float2bfloat16(a.s5[j]); return; }
}

// ---------------- fused LN1 + q-GEMM ----------------
__global__ void __launch_bounds__(256) ln1q_kernel(
    const float* __restrict__ x, const bf16* __restrict__ wq,
    const float* __restrict__ qbias, const float* __restrict__ g1,
    const float* __restrict__ b1, bf16* __restrict__ hb, bf16* __restrict__ qb)
{
  __shared__ bf16 Ws[64*72];
  __shared__ bf16 As[128*72];
  int t = threadIdx.x, w = t>>5, lane = t&31;
  size_t rowbase = (size_t)blockIdx.x * 128;

  for (int i = t; i < 512; i += 256){
    int row = i>>3, c8 = i&7;
    *(float4*)(Ws + row*72 + c8*8) = *(const float4*)(wq + row*64 + c8*8);
  }
  {
    int r = t>>1, half = t&1, col0 = half*32;
    const float* xr = x + (rowbase + r)*64 + col0;
    float v[32];
    #pragma unroll
    for (int j = 0; j < 8; j++) *(float4*)(v + j*4) = *(const float4*)(xr + j*4);
    float s = 0.f;
    #pragma unroll
    for (int j = 0; j < 32; j++) s += v[j];
    s += __shfl_xor_sync(0xffffffffu, s, 1);
    float mean = s * (1.0f/64.0f);
    float qv = 0.f;
    #pragma unroll
    for (int j = 0; j < 32; j++){ float d = v[j]-mean; qv += d*d; }
    qv += __shfl_xor_sync(0xffffffffu, qv, 1);
    float rstd = rsqrtf(qv*(1.0f/64.0f) + 1e-5f);
    #pragma unroll
    for (int j = 0; j < 16; j++){
      int c = col0 + 2*j;
      float2 gg = *(const float2*)(g1 + c);
      float2 bb = *(const float2*)(b1 + c);
      uint32_t u = pack2((v[2*j]-mean)*rstd*gg.x + bb.x,
                         (v[2*j+1]-mean)*rstd*gg.y + bb.y);
      *(uint32_t*)(As + r*72 + c) = u;
      *(uint32_t*)(hb + (rowbase + r)*64 + c) = u;
    }
  }
  __syncthreads();

  float acc[8][4];
  #pragma unroll
  for (int nb = 0; nb < 8; nb++){ acc[nb][0]=acc[nb][1]=acc[nb][2]=acc[nb][3]=0.f; }
  uint32_t As_u = (uint32_t)__cvta_generic_to_shared(As);
  uint32_t Ws_u = (uint32_t)__cvta_generic_to_shared(Ws);
  uint32_t a_base = As_u + ((w*16 + (lane&15))*72 + (lane>>4)*8)*2;
  uint32_t b_off  = (lane&15)*144 + (lane>>4)*16;
  #pragma unroll
  for (int kb = 0; kb < 4; kb++){
    uint32_t a[4];
    ldsm_x4(a, a_base + kb*32);
    uint32_t brow = Ws_u + (uint32_t)(kb*16)*144 + b_off;
    #pragma unroll
    for (int n2 = 0; n2 < 4; n2++){
      uint32_t b[4];
      ldsm_x4_t(b, brow + n2*32);
      mma_bf16(acc[2*n2  ][0],acc[2*n2  ][1],acc[2*n2  ][2],acc[2*n2  ][3],
               a[0],a[1],a[2],a[3], b[0],b[1]);
      mma_bf16(acc[2*n2+1][0],acc[2*n2+1][1],acc[2*n2+1][2],acc[2*n2+1][3],
               a[0],a[1],a[2],a[3], b[2],b[3]);
    }
  }
  int g = lane>>2, tq = lane&3;
  size_t r0 = rowbase + w*16 + g, r1 = r0 + 8;
  #pragma unroll
  for (int nb = 0; nb < 8; nb++){
    int col = nb*8 + tq*2;
    float b0 = qbias[col], b1v = qbias[col+1];
    *(uint32_t*)(qb + r0*64 + col) = pack2((acc[nb][0]+b0)*0.125f, (acc[nb][1]+b1v)*0.125f);
    *(uint32_t*)(qb + r1*64 + col) = pack2((acc[nb][2]+b0)*0.125f, (acc[nb][3]+b1v)*0.125f);
  }
}

// ---------------- sr conv (split-K mma) ----------------
__global__ void __launch_bounds__(256) conv_mma(
    const bf16* __restrict__ h, const bf16* __restrict__ wsr,
    float* __restrict__ part)
{
  __shared__ bf16 Ws[64*72];
  __shared__ bf16 As[128*72];
  int t = threadIdx.x, w = t>>5, lane = t&31;
  int r1 = blockIdx.y;
  int pbase = blockIdx.x * 128;

  float acc[8][4];
  #pragma unroll
  for (int nb = 0; nb < 8; nb++){ acc[nb][0]=acc[nb][1]=acc[nb][2]=acc[nb][3]=0.f; }
  uint32_t As_u = (uint32_t)__cvta_generic_to_shared(As);
  uint32_t Ws_u = (uint32_t)__cvta_generic_to_shared(Ws);
  uint32_t a_base = As_u + ((w*16 + (lane&15))*72 + (lane>>4)*8)*2;
  uint32_t b_off  = (lane&15)*144 + (lane>>4)*16;

  for (int kk = 0; kk < 8; kk++){
    __syncthreads();
    for (int i = t; i < 512; i += 256){
      int row = i>>3, c8 = i&7;
      *(float4*)(Ws + row*72 + c8*8) =
        *(const float4*)(wsr + ((size_t)(r1*512 + kk*64 + row))*64 + c8*8);
    }
    for (int i = t; i < 1024; i += 256){
      int r = i>>3, c8 = i&7;
      int p = pbase + r;
      int b = p>>8, ph = (p>>4)&15, pw = p&15;
      size_t src = ((((size_t)b*128 + ph*8 + r1)*128) + pw*8)*64 + kk*64 + c8*8;
      *(float4*)(As + r*72 + c8*8) = *(const float4*)(h + src);
    }
    __syncthreads();
    #pragma unroll
    for (int kb = 0; kb < 4; kb++){
      uint32_t a[4];
      ldsm_x4(a, a_base + kb*32);
      uint32_t brow = Ws_u + (uint32_t)(kb*16)*144 + b_off;
      #pragma unroll
      for (int n2 = 0; n2 < 4; n2++){
        uint32_t b[4];
        ldsm_x4_t(b, brow + n2*32);
        mma_bf16(acc[2*n2  ][0],acc[2*n2  ][1],acc[2*n2  ][2],acc[2*n2  ][3],
                 a[0],a[1],a[2],a[3], b[0],b[1]);
        mma_bf16(acc[2*n2+1][0],acc[2*n2+1][1],acc[2*n2+1][2],acc[2*n2+1][3],
                 a[0],a[1],a[2],a[3], b[2],b[3]);
      }
    }
  }
  int g = lane>>2, tq = lane&3;
  size_t p0 = pbase + w*16 + g, p1 = p0 + 8;
  #pragma unroll
  for (int nb = 0; nb < 8; nb++){
    int col = nb*8 + tq*2;
    *(float2*)(part + ((size_t)r1*2048 + p0)*64 + col) = make_float2(acc[nb][0], acc[nb][1]);
    *(float2*)(part + ((size_t)r1*2048 + p1)*64 + col) = make_float2(acc[nb][2], acc[nb][3]);
  }
}

// ---------------- fused: reduce conv partials + srn-LN + kv GEMM ----------------
__global__ void __launch_bounds__(256) kv_fused(
    const float* __restrict__ part, const float* __restrict__ srb,
    const float* __restrict__ gamma, const float* __restrict__ beta,
    const bf16* __restrict__ wkv, const float* __restrict__ kvbias,
    bf16* __restrict__ kvout)
{
  __shared__ bf16 Ws[64*136];
  __shared__ bf16 As[128*72];
  int t = threadIdx.x, w = t>>5, lane = t&31;
  size_t rowbase = (size_t)blockIdx.x * 128;

  for (int i = t; i < 1024; i += 256){
    int row = i>>4, c8 = i&15;
    *(float4*)(Ws + row*136 + c8*8) = *(const float4*)(wkv + row*128 + c8*8);
  }
  {
    int r = t>>1, half = t&1, col0 = half*32;
    float v[32];
    #pragma unroll
    for (int j = 0; j < 8; j++) *(float4*)(v + j*4) = make_float4(0.f,0.f,0.f,0.f);
    #pragma unroll
    for (int s = 0; s < 8; s++){
      const float* p = part + ((size_t)s*2048 + rowbase + r)*64 + col0;
      #pragma unroll
      for (int j = 0; j < 8; j++){
        float4 q = *(const float4*)(p + j*4);
        v[4*j] += q.x; v[4*j+1] += q.y; v[4*j+2] += q.z; v[4*j+3] += q.w;
      }
    }
    #pragma unroll
    for (int j = 0; j < 8; j++){
      float4 q = *(const float4*)(srb + col0 + j*4);
      v[4*j] += q.x; v[4*j+1] += q.y; v[4*j+2] += q.z; v[4*j+3] += q.w;
    }
    float s = 0.f;
    #pragma unroll
    for (int j = 0; j < 32; j++) s += v[j];
    s += __shfl_xor_sync(0xffffffffu, s, 1);
    float mean = s * (1.0f/64.0f);
    float qv = 0.f;
    #pragma unroll
    for (int j = 0; j < 32; j++){ float d = v[j]-mean; qv += d*d; }
    qv += __shfl_xor_sync(0xffffffffu, qv, 1);
    float rstd = rsqrtf(qv*(1.0f/64.0f) + 1e-5f);
    #pragma unroll
    for (int j = 0; j < 16; j++){
      int c = col0 + 2*j;
      float2 gg = *(const float2*)(gamma + c);
      float2 bb = *(const float2*)(beta + c);
      *(uint32_t*)(As + r*72 + c) = pack2((v[2*j]-mean)*rstd*gg.x + bb.x,
                                          (v[2*j+1]-mean)*rstd*gg.y + bb.y);
    }
  }
  __syncthreads();

  float acc[16][4];
  #pragma unroll
  for (int nb = 0; nb < 16; nb++){ acc[nb][0]=acc[nb][1]=acc[nb][2]=acc[nb][3]=0.f; }
  uint32_t As_u = (uint32_t)__cvta_generic_to_shared(As);
  uint32_t Ws_u = (uint32_t)__cvta_generic_to_shared(Ws);
  uint32_t a_base = As_u + ((w*16 + (lane&15))*72 + (lane>>4)*8)*2;
  uint32_t b_off  = (lane&15)*272 + (lane>>4)*16;
  #pragma unroll
  for (int kb = 0; kb < 4; kb++){
    uint32_t a[4];
    ldsm_x4(a, a_base + kb*32);
    uint32_t brow = Ws_u + (uint32_t)(kb*16)*272 + b_off;
    #pragma unroll
    for (int n2 = 0; n2 < 8; n2++){
      uint32_t b[4];
      ldsm_x4_t(b, brow + n2*32);
      mma_bf16(acc[2*n2  ][0],acc[2*n2  ][1],acc[2*n2  ][2],acc[2*n2  ][3],
               a[0],a[1],a[2],a[3], b[0],b[1]);
      mma_bf16(acc[2*n2+1][0],acc[2*n2+1][1],acc[2*n2+1][2],acc[2*n2+1][3],
               a[0],a[1],a[2],a[3], b[2],b[3]);
    }
  }
  int g = lane>>2, tq = lane&3;
  size_t r0 = rowbase + w*16 + g, r1 = r0 + 8;
  #pragma unroll
  for (int nb = 0; nb < 16; nb++){
    int col = nb*8 + tq*2;
    float b0 = kvbias[col], b1 = kvbias[col+1];
    *(uint32_t*)(kvout + r0*128 + col) = pack2(acc[nb][0]+b0, acc[nb][1]+b1);
    *(uint32_t*)(kvout + r1*128 + col) = pack2(acc[nb][2]+b0, acc[nb][3]+b1);
  }
}

// ---- attention + proj + residual + LN2 + fc1 (all fused) ----
__global__ void __launch_bounds__(256) attn_fused(
    const bf16* __restrict__ q, const bf16* __restrict__ kv,
    const bf16* __restrict__ wp, const float* __restrict__ pbias,
    const float* __restrict__ x, const float* __restrict__ g2,
    const float* __restrict__ b2, const bf16* __restrict__ w1,
    const float* __restrict__ fc1b, float* __restrict__ x2,
    bf16* __restrict__ fbout)
{
  extern __shared__ bf16 sma[];
  bf16* Qs = sma;              // 128 x 72
  bf16* Ks = sma + 128*72;     // 256 x 72 -> reused for w1 (64 x 264)
  bf16* Vs = Ks  + 256*72;     // 256 x 72
  bf16* Ps = Vs  + 256*72;     // 64 x 72
  int t = threadIdx.x, w = t>>5, lane = t&31;
  int b = blockIdx.y;
  size_t qrow0 = (size_t)b*NTOK + (size_t)blockIdx.x*128;
  const bf16* kvb = kv + (size_t)b*NRTOK*128;

  for (int i = t; i < 1024; i += 256){
    int r = i>>3, c8 = i&7;
    *(float4*)(Qs + r*72 + c8*8) = *(const float4*)(q + (qrow0 + r)*64 + c8*8);
  }
  for (int i = t; i < 2048; i += 256){
    int r = i>>3, c8 = i&7;
    *(float4*)(Ks + r*72 + c8*8) = *(const float4*)(kvb + (size_t)r*128 + c8*8);
  }
  for (int i = t; i < 2048; i += 256){
    int r = i>>3, c8 = i&7;
    *(float4*)(Vs + r*72 + c8*8) = *(const float4*)(kvb + (size_t)r*128 + 64 + c8*8);
  }
  for (int i = t; i < 512; i += 256){
    int r = i>>3, c8 = i&7;
    *(float4*)(Ps + r*72 + c8*8) = *(const float4*)(wp + r*64 + c8*8);
  }
  __syncthreads();

  uint32_t Qs_u = (uint32_t)__cvta_generic_to_shared(Qs);
  uint32_t Ks_u = (uint32_t)__cvta_generic_to_shared(Ks);
  uint32_t Vs_u = (uint32_t)__cvta_generic_to_shared(Vs);
  uint32_t Ps_u = (uint32_t)__cvta_generic_to_shared(Ps);
  uint32_t a_base = Qs_u + ((w*16 + (lane&15))*72 + (lane>>4)*8)*2;
  uint32_t k_off = ((((lane>>4)&1)*8 + (lane&7)))*144 + ((lane>>3)&1)*16;
  uint32_t v_off = (lane&15)*144 + (lane>>4)*16;

  float s[32][4];
  #pragma unroll
  for (int nb = 0; nb < 32; nb++){ s[nb][0]=s[nb][1]=s[nb][2]=s[nb][3]=0.f; }

  #pragma unroll
  for (int kb = 0; kb < 4; kb++){
    uint32_t a[4];
    ldsm_x4(a, a_base + kb*32);
    #pragma unroll
    for (int ng = 0; ng < 16; ng++){
      uint32_t bb[4];
      ldsm_x4(bb, Ks_u + (uint32_t)ng*2304 + kb*32 + k_off);
      mma_bf16(s[2*ng  ][0],s[2*ng  ][1],s[2*ng  ][2],s[2*ng  ][3],
               a[0],a[1],a[2],a[3], bb[0],bb[1]);
      mma_bf16(s[2*ng+1][0],s[2*ng+1][1],s[2*ng+1][2],s[2*ng+1][3],
               a[0],a[1],a[2],a[3], bb[2],bb[3]);
    }
  }

  // softmax over 256 keys
  float mx0 = -1e30f, mx1 = -1e30f;
  #pragma unroll
  for (int nb = 0; nb < 32; nb++){
    mx0 = fmaxf(mx0, fmaxf(s[nb][0], s[nb][1]));
    mx1 = fmaxf(mx1, fmaxf(s[nb][2], s[nb][3]));
  }
  mx0 = fmaxf(mx0, __shfl_xor_sync(0xffffffffu, mx0, 1));
  mx0 = fmaxf(mx0, __shfl_xor_sync(0xffffffffu, mx0, 2));
  mx1 = fmaxf(mx1, __shfl_xor_sync(0xffffffffu, mx1, 1));
  mx1 = fmaxf(mx1, __shfl_xor_sync(0xffffffffu, mx1, 2));
  float sm0 = 0.f, sm1 = 0.f;
  #pragma unroll
  for (int nb = 0; nb < 32; nb++){
    s[nb][0] = __expf(s[nb][0] - mx0); sm0 += s[nb][0];
    s[nb][1] = __expf(s[nb][1] - mx0); sm0 += s[nb][1];
    s[nb][2] = __expf(s[nb][2] - mx1); sm1 += s[nb][2];
    s[nb][3] = __expf(s[nb][3] - mx1); sm1 += s[nb][3];
  }
  sm0 += __shfl_xor_sync(0xffffffffu, sm0, 1);
  sm0 += __shfl_xor_sync(0xffffffffu, sm0, 2);
  sm1 += __shfl_xor_sync(0xffffffffu, sm1, 1);
  sm1 += __shfl_xor_sync(0xffffffffu, sm1, 2);
  float inv0 = __frcp_rn(sm0), inv1 = __frcp_rn(sm1);
  #pragma unroll
  for (int nb = 0; nb < 32; nb++){
    s[nb][0] *= inv0; s[nb][1] *= inv0; s[nb][2] *= inv1; s[nb][3] *= inv1;
  }

  // Ks is dead from here: async-load w1 (64x256 -> stride 264) into its space.
  __syncthreads();
  for (int i = t; i < 2048; i += 256){
    int row = i>>5, c8 = i&31;
    cp_async16(Ks_u + (uint32_t)(row*264 + c8*8)*2, w1 + (size_t)row*256 + c8*8);
  }
  cp_async_commit();

  // O = P @ V
  float oo[8][4];
  #pragma unroll
  for (int nb = 0; nb < 8; nb++){ oo[nb][0]=oo[nb][1]=oo[nb][2]=oo[nb][3]=0.f; }
  #pragma unroll
  for (int kb = 0; kb < 16; kb++){
    uint32_t a0 = pack2(s[2*kb  ][0], s[2*kb  ][1]);
    uint32_t a1 = pack2(s[2*kb  ][2], s[2*kb  ][3]);
    uint32_t a2 = pack2(s[2*kb+1][0], s[2*kb+1][1]);
    uint32_t a3 = pack2(s[2*kb+1][2], s[2*kb+1][3]);
    uint32_t base = Vs_u + (uint32_t)kb*16*144 + v_off;
    #pragma unroll
    for (int n2 = 0; n2 < 4; n2++){
      uint32_t bb[4];
      ldsm_x4_t(bb, base + n2*32);
      mma_bf16(oo[2*n2  ][0],oo[2*n2  ][1],oo[2*n2  ][2],oo[2*n2  ][3],
               a0,a1,a2,a3, bb[0],bb[1]);
      mma_bf16(oo[2*n2+1][0],oo[2*n2+1][1],oo[2*n2+1][2],oo[2*n2+1][3],
               a0,a1,a2,a3, bb[2],bb[3]);
    }
  }

  // proj GEMM
  float acc2[8][4];
  #pragma unroll
  for (int nb = 0; nb < 8; nb++){ acc2[nb][0]=acc2[nb][1]=acc2[nb][2]=acc2[nb][3]=0.f; }
  #pragma unroll
  for (int kb = 0; kb < 4; kb++){
    uint32_t a0 = pack2(oo[2*kb  ][0], oo[2*kb  ][1]);
    uint32_t a1 = pack2(oo[2*kb  ][2], oo[2*kb  ][3]);
    uint32_t a2 = pack2(oo[2*kb+1][0], oo[2*kb+1][1]);
    uint32_t a3 = pack2(oo[2*kb+1][2], oo[2*kb+1][3]);
    uint32_t brow = Ps_u + (uint32_t)kb*16*144 + v_off;
    #pragma unroll
    for (int n2 = 0; n2 < 4; n2++){
      uint32_t bb[4];
      ldsm_x4_t(bb, brow + n2*32);
      mma_bf16(acc2[2*n2  ][0],acc2[2*n2  ][1],acc2[2*n2  ][2],acc2[2*n2  ][3],
               a0,a1,a2,a3, bb[0],bb[1]);
      mma_bf16(acc2[2*n2+1][0],acc2[2*n2+1][1],acc2[2*n2+1][2],acc2[2*n2+1][3],
               a0,a1,a2,a3, bb[2],bb[3]);
    }
  }

  // epilogue: x2 = x + proj; hn = LN2(x2)
  int g = lane>>2, tq = lane&3;
  size_t r0 = qrow0 + w*16 + g, r1 = r0 + 8;
  float v0[16], v1[16];
  float s0 = 0.f, s1 = 0.f;
  #pragma unroll
  for (int nb = 0; nb < 8; nb++){
    int col = nb*8 + tq*2;
    float pb0 = pbias[col], pb1 = pbias[col+1];
    float2 xx0 = *(const float2*)(x + r0*64 + col);
    float2 xx1 = *(const float2*)(x + r1*64 + col);
    v0[2*nb]   = acc2[nb][0] + pb0 + xx0.x;
    v0[2*nb+1] = acc2[nb][1] + pb1 + xx0.y;
    v1[2*nb]   = acc2[nb][2] + pb0 + xx1.x;
    v1[2*nb+1] = acc2[nb][3] + pb1 + xx1.y;
    s0 += v0[2*nb] + v0[2*nb+1];
    s1 += v1[2*nb] + v1[2*nb+1];
  }
  s0 += __shfl_xor_sync(0xffffffffu, s0, 1);
  s0 += __shfl_xor_sync(0xffffffffu, s0, 2);
  s1 += __shfl_xor_sync(0xffffffffu, s1, 1);
  s1 += __shfl_xor_sync(0xffffffffu, s1, 2);
  float m0 = s0*(1.0f/64.0f), m1 = s1*(1.0f/64.0f);
  float q0 = 0.f, q1 = 0.f;
  #pragma unroll
  for (int j = 0; j < 16; j++){
    float d0 = v0[j]-m0, d1 = v1[j]-m1;
    q0 += d0*d0; q1 += d1*d1;
  }
  q0 += __shfl_xor_sync(0xffffffffu, q0, 1);
  q0 += __shfl_xor_sync(0xffffffffu, q0, 2);
  q1 += __shfl_xor_sync(0xffffffffu, q1, 1);
  q1 += __shfl_xor_sync(0xffffffffu, q1, 2);
  float rs0 = rsqrtf(q0*(1.0f/64.0f) + 1e-5f);
  float rs1 = rsqrtf(q1*(1.0f/64.0f) + 1e-5f);

  float hn0[16], hn1[16];
  #pragma unroll
  for (int nb = 0; nb < 8; nb++){
    int col = nb*8 + tq*2;
    *(float2*)(x2 + r0*64 + col) = make_float2(v0[2*nb], v0[2*nb+1]);
    *(float2*)(x2 + r1*64 + col) = make_float2(v1[2*nb], v1[2*nb+1]);
    float2 gg = *(const float2*)(g2 + col);
    float2 bb = *(const float2*)(b2 + col);
    hn0[2*nb]   = (v0[2*nb]  -m0)*rs0*gg.x + bb.x;
    hn0[2*nb+1] = (v0[2*nb+1]-m0)*rs0*gg.y + bb.y;
    hn1[2*nb]   = (v1[2*nb]  -m1)*rs1*gg.x + bb.x;
    hn1[2*nb+1] = (v1[2*nb+1]-m1)*rs1*gg.y + bb.y;
  }

  // fc1: f = hn @ w1 + fc1b  (two 128-col halves), w1 in Ks region (stride 264)
  cp_async_wait0();
  __syncthreads();
  uint32_t b_off1 = (lane&15)*528 + (lane>>4)*16;
  #pragma unroll
  for (int h = 0; h < 2; h++){
    float fa[16][4];
    #pragma unroll
    for (int nb = 0; nb < 16; nb++){ fa[nb][0]=fa[nb][1]=fa[nb][2]=fa[nb][3]=0.f; }
    #pragma unroll
    for (int kb = 0; kb < 4; kb++){
      uint32_t a0 = pack2(hn0[4*kb],   hn0[4*kb+1]);
      uint32_t a1 = pack2(hn1[4*kb],   hn1[4*kb+1]);
      uint32_t a2 = pack2(hn0[4*kb+2], hn0[4*kb+3]);
      uint32_t a3 = pack2(hn1[4*kb+2], hn1[4*kb+3]);
      uint32_t brow = Ks_u + (uint32_t)(kb*16)*528 + h*256 + b_off1;
      #pragma unroll
      for (int n2 = 0; n2 < 8; n2++){
        uint32_t bb[4];
        ldsm_x4_t(bb, brow + n2*32);
        mma_bf16(fa[2*n2  ][0],fa[2*n2  ][1],fa[2*n2  ][2],fa[2*n2  ][3],
                 a0,a1,a2,a3, bb[0],bb[1]);
        mma_bf16(fa[2*n2+1][0],fa[2*n2+1][1],fa[2*n2+1][2],fa[2*n2+1][3],
                 a0,a1,a2,a3, bb[2],bb[3]);
      }
    }
    #pragma unroll
    for (int nb = 0; nb < 16; nb++){
      int col = h*128 + nb*8 + tq*2;
      float b0 = fc1b[col], b1 = fc1b[col+1];
      *(uint32_t*)(fbout + r0*256 + col) = pack2(fa[nb][0]+b0, fa[nb][1]+b1);
      *(uint32_t*)(fbout + r1*256 + col) = pack2(fa[nb][2]+b0, fa[nb][3]+b1);
    }
  }
}

// ---------------- fused dwconv3x3 + GELU + fc2 + residual ----------------
__global__ void __launch_bounds__(256) fc2_fused(
    const bf16* __restrict__ f, const float* __restrict__ dw,
    const bf16* __restrict__ w2, const float* __restrict__ bias2,
    const float* __restrict__ x2, float* __restrict__ out)
{
  extern __shared__ bf16 smf[];
  bf16* Ws = smf;                 // 256 x 72
  bf16* Fs = smf + 256*72;        // 3 x 128 x 72
  bf16* Gs = Fs  + 3*128*72;      // 128 x 72
  int t = threadIdx.x, w = t>>5, lane = t&31;
  int by = blockIdx.x;
  int b = by >> 7, y = by & 127;
  size_t tokbase = (size_t)b*NTOK + (size_t)y*128;

  for (int i = t; i < 2048; i += 256){
    int row = i>>3, c8 = i&7;
    *(float4*)(Ws + row*72 + c8*8) = *(const float4*)(w2 + row*64 + c8*8);
  }

  float acc[8][4];
  #pragma unroll
  for (int nb = 0; nb < 8; nb++){ acc[nb][0]=acc[nb][1]=acc[nb][2]=acc[nb][3]=0.f; }
  uint32_t Ws_u = (uint32_t)__cvta_generic_to_shared(Ws);
  uint32_t Gs_u = (uint32_t)__cvta_generic_to_shared(Gs);
  uint32_t a_base = Gs_u + ((w*16 + (lane&15))*72 + (lane>>4)*8)*2;
  uint32_t b_off  = (lane&15)*144 + (lane>>4)*16;

  int chl = lane*2;
  int px0 = w*16;

  for (int kc = 0; kc < 256; kc += 64){
    __syncthreads();
    for (int i = t; i < 3072; i += 256){
      int row3 = i>>10, rem = i&1023, px = rem>>3, c8 = rem&7;
      int yy = y + row3 - 1;
      float4 val;
      if (yy >= 0 && yy < 128)
        val = *(const float4*)(f + ((size_t)b*NTOK + (size_t)yy*128 + px)*256 + kc + c8*8);
      else
        val = make_float4(0.f,0.f,0.f,0.f);
      *(float4*)(Fs + row3*9216 + px*72 + c8*8) = val;
    }
    __syncthreads();
    {
      float w9[2][9];
      #pragma unroll
      for (int i = 0; i < 9; i++){
        float2 wv = *(const float2*)(dw + i*256 + kc + chl);
        w9[0][i] = wv.x; w9[1][i] = wv.y;
      }
      uint32_t colv[3][3];
      #pragma unroll
      for (int dy = 0; dy < 3; dy++){
        colv[0][dy] = (px0 > 0) ? *(uint32_t*)(Fs + dy*9216 + (px0-1)*72 + chl) : 0u;
        colv[1][dy] = *(uint32_t*)(Fs + dy*9216 + px0*72 + chl);
      }
      #pragma unroll
      for (int pi = 0; pi < 16; pi++){
        int px = px0 + pi;
        #pragma unroll
        for (int dy = 0; dy < 3; dy++)
          colv[2][dy] = (px+1 < 128) ? *(uint32_t*)(Fs + dy*9216 + (px+1)*72 + chl) : 0u;
        float a0 = 0.f, a1 = 0.f;
        #pragma unroll
        for (int dy = 0; dy < 3; dy++)
          #pragma unroll
          for (int dx = 0; dx < 3; dx++){
            float2 vv = __bfloat1622float2(
                *reinterpret_cast<const __nv_bfloat162*>(&colv[dx][dy]));
            a0 = fmaf(vv.x, w9[0][dy*3+dx], a0);
            a1 = fmaf(vv.y, w9[1][dy*3+dx], a1);
          }
        a0 = 0.5f*a0*(1.0f + erff(a0*0.70710678118654752f));
        a1 = 0.5f*a1*(1.0f + erff(a1*0.70710678118654752f));
        *(uint32_t*)(Gs + px*72 + chl) = pack2(a0, a1);
        #pragma unroll
        for (int dy = 0; dy < 3; dy++){ colv[0][dy] = colv[1][dy]; colv[1][dy] = colv[2][dy]; }
      }
    }
    __syncwarp();
    #pragma unroll
    for (int kb = 0; kb < 4; kb++){
      uint32_t a[4];
      ldsm_x4(a, a_base + kb*32);
      uint32_t brow = Ws_u + (uint32_t)(kc + kb*16)*144 + b_off;
      #pragma unroll
      for (int n2 = 0; n2 < 4; n2++){
        uint32_t bb[4];
        ldsm_x4_t(bb, brow + n2*32);
        mma_bf16(acc[2*n2  ][0],acc[2*n2  ][1],acc[2*n2  ][2],acc[2*n2  ][3],
                 a[0],a[1],a[2],a[3], bb[0],bb[1]);
        mma_bf16(acc[2*n2+1][0],acc[2*n2+1][1],acc[2*n2+1][2],acc[2*n2+1][3],
                 a[0],a[1],a[2],a[3], bb[2],bb[3]);
      }
    }
  }

  int g = lane>>2, tq = lane&3;
  size_t r0 = tokbase + w*16 + g, r1 = r0 + 8;
  #pragma unroll
  for (int nb = 0; nb < 8; nb++){
    int col = nb*8 + tq*2;
    float b0 = bias2[col], b1 = bias2[col+1];
    float2 q0 = *(const float2*)(x2 + r0*64 + col);
    float2 q1 = *(const float2*)(x2 + r1*64 + col);
    *(float2*)(out + r0*64 + col) = make_float2(acc[nb][0]+b0+q0.x, acc[nb][1]+b1+q0.y);
    *(float2*)(out + r1*64 + col) = make_float2(acc[nb][2]+b0+q1.x, acc[nb][3]+b1+q1.y);
  }
}

// ---------------- launch ----------------
extern "C" void kernel_launch(void* const* d_in, const int* in_sizes, int n_in,
                              void* d_out, int out_size)
{
  const float* x      = (const float*)d_in[0];
  const float* ln1_g  = (const float*)d_in[3];
  const float* ln1_b  = (const float*)d_in[4];
  const float* q_w    = (const float*)d_in[5];
  const float* q_b    = (const float*)d_in[6];
  const float* kv_w   = (const float*)d_in[7];
  const float* kv_b   = (const float*)d_in[8];
  const float* proj_w = (const float*)d_in[9];
  const float* proj_b = (const float*)d_in[10];
  const float* sr_w   = (const float*)d_in[11];
  const float* sr_b   = (const float*)d_in[12];
  const float* srn_g  = (const float*)d_in[13];
  const float* srn_b  = (const float*)d_in[14];
  const float* ln2_g  = (const float*)d_in[15];
  const float* ln2_b  = (const float*)d_in[16];
  const float* fc1_w  = (const float*)d_in[17];
  const float* fc1_b  = (const float*)d_in[18];
  const float* dw_w   = (const float*)d_in[19];
  const float* fc2_w  = (const float*)d_in[20];
  const float* fc2_b  = (const float*)d_in[21];
  float* out = (float*)d_out;

  bf16 *hb,*qb,*fb,*kvbuf,*wq,*wkv,*wp,*wsr,*w1,*w2;
  float *x2,*convp;
  cudaGetSymbolAddress((void**)&hb,  g_hb);
  cudaGetSymbolAddress((void**)&qb,  g_qb);
  cudaGetSymbolAddress((void**)&x2,  g_x2);
  cudaGetSymbolAddress((void**)&fb,  g_fb);
  cudaGetSymbolAddress((void**)&convp, g_convp);
  cudaGetSymbolAddress((void**)&kvbuf, g_kvb);
  cudaGetSymbolAddress((void**)&wq,  g_wq);
  cudaGetSymbolAddress((void**)&wkv, g_wkv);
  cudaGetSymbolAddress((void**)&wp,  g_wp);
  cudaGetSymbolAddress((void**)&wsr, g_wsr);
  cudaGetSymbolAddress((void**)&w1,  g_w1);
  cudaGetSymbolAddress((void**)&w2,  g_w2);

  const int SM_ATTN = (128 + 256 + 256 + 64)*72*2;    // 101376
  const int SM_FC2  = (256 + 3*128 + 128)*72*2;       // 110592

  cudaFuncSetAttribute((const void*)attn_fused,
                       cudaFuncAttributeMaxDynamicSharedMemorySize, SM_ATTN);
  cudaFuncSetAttribute((const void*)fc2_fused,
                       cudaFuncAttributeMaxDynamicSharedMemorySize, SM_FC2);

  CvtArgs ca = { q_w, kv_w, proj_w, sr_w, fc1_w, fc2_w, wq, wkv, wp, wsr, w1, w2 };
  cvt_all<<<1216, 256>>>(ca);
  ln1q_kernel<<<1024, 256>>>(x, wq, q_b, ln1_g, ln1_b, hb, qb);
  conv_mma<<<dim3(16,8), 256>>>(hb, wsr, convp);
  kv_fused<<<16, 256>>>(convp, sr_b, srn_g, srn_b, wkv, kv_b, kvbuf);
  attn_fused<<<dim3(128, BB), 256, SM_ATTN>>>(qb, kvbuf, wp, proj_b, x,
                                              ln2_g, ln2_b, w1, fc1_b, x2, fb);
  fc2_fused<<<1024, 256, SM_FC2>>>(fb, dw_w, w2, fc2_b, x2, out);
}

// round 5
// speedup vs baseline: 3.3709x; 1.1174x over previous
#include <cuda_runtime.h>
#include <cuda_bf16.h>
#include <math.h>
#include <stdint.h>

typedef __nv_bfloat16 bf16;

#define BB    8
#define NTOK  16384
#define CC    64
#define HIDD  256
#define NRTOK 256
#define MTOT  (BB*NTOK)   // 131072

// ---------------- scratch ----------------
__device__ bf16  g_hb [(size_t)MTOT*CC];
__device__ bf16  g_qb [(size_t)MTOT*CC];
__device__ float g_x2 [(size_t)MTOT*CC];
__device__ bf16  g_fb [(size_t)MTOT*HIDD];
__device__ float g_convp[(size_t)8*2048*CC];
__device__ bf16  g_kvb[(size_t)2048*2*CC];
__device__ bf16  g_wq [64*64];
__device__ bf16  g_wkv[64*128];
__device__ bf16  g_wp [64*64];
__device__ bf16  g_wsr[4096*64];
__device__ bf16  g_w1 [64*256];
__device__ bf16  g_w2 [256*64];

// ---------------- helpers ----------------
__device__ __forceinline__ void mma_bf16(float& d0,float& d1,float& d2,float& d3,
    uint32_t a0,uint32_t a1,uint32_t a2,uint32_t a3,uint32_t b0,uint32_t b1){
  asm volatile("mma.sync.aligned.m16n8k16.row.col.f32.bf16.bf16.f32 "
    "{%0,%1,%2,%3}, {%4,%5,%6,%7}, {%8,%9}, {%0,%1,%2,%3};\n"
    : "+f"(d0),"+f"(d1),"+f"(d2),"+f"(d3)
    : "r"(a0),"r"(a1),"r"(a2),"r"(a3),"r"(b0),"r"(b1));
}
__device__ __forceinline__ void ldsm_x4(uint32_t* r, uint32_t addr){
  asm volatile("ldmatrix.sync.aligned.m8n8.x4.shared.b16 {%0,%1,%2,%3}, [%4];\n"
    : "=r"(r[0]),"=r"(r[1]),"=r"(r[2]),"=r"(r[3]) : "r"(addr));
}
__device__ __forceinline__ void ldsm_x4_t(uint32_t* r, uint32_t addr){
  asm volatile("ldmatrix.sync.aligned.m8n8.x4.trans.shared.b16 {%0,%1,%2,%3}, [%4];\n"
    : "=r"(r[0]),"=r"(r[1]),"=r"(r[2]),"=r"(r[3]) : "r"(addr));
}
__device__ __forceinline__ uint32_t pack2(float lo, float hi){
  __nv_bfloat162 v = __floats2bfloat162_rn(lo, hi);
  return reinterpret_cast<uint32_t&>(v);
}
__device__ __forceinline__ void cp_async16(uint32_t saddr, const void* gptr){
  asm volatile("cp.async.ca.shared.global [%0], [%1], 16;\n" :: "r"(saddr), "l"(gptr));
}
__device__ __forceinline__ void cp_async_commit(){ asm volatile("cp.async.commit_group;\n"); }
__device__ __forceinline__ void cp_async_wait0(){ asm volatile("cp.async.wait_group 0;\n"); }

// ---------------- weight conversions ----------------
struct CvtArgs {
  const float* s0; const float* s1; const float* s2;
  const float* s3; const float* s4; const float* s5;
  bf16 *d0,*d1,*d2,*d3,*d4,*d5;
};
__global__ void __launch_bounds__(256) cvt_all(CvtArgs a){
  int i = blockIdx.x*256 + threadIdx.x;
  if (i < 4096)                { a.d0[i] = __float2bfloat16(a.s0[i]); return; }
  if (i < 12288)               { int j=i-4096;   a.d1[j] = __float2bfloat16(a.s1[j]); return; }
  if (i < 16384)               { int j=i-12288;  a.d2[j] = __float2bfloat16(a.s2[j]); return; }
  if (i < 278528)              { int j=i-16384;  a.d3[j] = __float2bfloat16(a.s3[j]); return; }
  if (i < 294912)              { int j=i-278528; a.d4[j] = __float2bfloat16(a.s4[j]); return; }
  if (i < 311296)              { int j=i-294912; a.d5[j] = __float2bfloat16(a.s5[j]); return; }
}

// ---------------- fused LN1 + q-GEMM ----------------
__global__ void __launch_bounds__(256) ln1q_kernel(
    const float* __restrict__ x, const bf16* __restrict__ wq,
    const float* __restrict__ qbias, const float* __restrict__ g1,
    const float* __restrict__ b1, bf16* __restrict__ hb, bf16* __restrict__ qb)
{
  __shared__ bf16 Ws[64*72];
  __shared__ bf16 As[128*72];
  int t = threadIdx.x, w = t>>5, lane = t&31;
  size_t rowbase = (size_t)blockIdx.x * 128;

  for (int i = t; i < 512; i += 256){
    int row = i>>3, c8 = i&7;
    *(float4*)(Ws + row*72 + c8*8) = *(const float4*)(wq + row*64 + c8*8);
  }
  {
    int r = t>>1, half = t&1, col0 = half*32;
    const float* xr = x + (rowbase + r)*64 + col0;
    float v[32];
    #pragma unroll
    for (int j = 0; j < 8; j++) *(float4*)(v + j*4) = *(const float4*)(xr + j*4);
    float s = 0.f;
    #pragma unroll
    for (int j = 0; j < 32; j++) s += v[j];
    s += __shfl_xor_sync(0xffffffffu, s, 1);
    float mean = s * (1.0f/64.0f);
    float qv = 0.f;
    #pragma unroll
    for (int j = 0; j < 32; j++){ float d = v[j]-mean; qv += d*d; }
    qv += __shfl_xor_sync(0xffffffffu, qv, 1);
    float rstd = rsqrtf(qv*(1.0f/64.0f) + 1e-5f);
    #pragma unroll
    for (int j = 0; j < 16; j++){
      int c = col0 + 2*j;
      float2 gg = *(const float2*)(g1 + c);
      float2 bb = *(const float2*)(b1 + c);
      uint32_t u = pack2((v[2*j]-mean)*rstd*gg.x + bb.x,
                         (v[2*j+1]-mean)*rstd*gg.y + bb.y);
      *(uint32_t*)(As + r*72 + c) = u;
      *(uint32_t*)(hb + (rowbase + r)*64 + c) = u;
    }
  }
  __syncthreads();

  float acc[8][4];
  #pragma unroll
  for (int nb = 0; nb < 8; nb++){ acc[nb][0]=acc[nb][1]=acc[nb][2]=acc[nb][3]=0.f; }
  uint32_t As_u = (uint32_t)__cvta_generic_to_shared(As);
  uint32_t Ws_u = (uint32_t)__cvta_generic_to_shared(Ws);
  uint32_t a_base = As_u + ((w*16 + (lane&15))*72 + (lane>>4)*8)*2;
  uint32_t b_off  = (lane&15)*144 + (lane>>4)*16;
  #pragma unroll
  for (int kb = 0; kb < 4; kb++){
    uint32_t a[4];
    ldsm_x4(a, a_base + kb*32);
    uint32_t brow = Ws_u + (uint32_t)(kb*16)*144 + b_off;
    #pragma unroll
    for (int n2 = 0; n2 < 4; n2++){
      uint32_t b[4];
      ldsm_x4_t(b, brow + n2*32);
      mma_bf16(acc[2*n2  ][0],acc[2*n2  ][1],acc[2*n2  ][2],acc[2*n2  ][3],
               a[0],a[1],a[2],a[3], b[0],b[1]);
      mma_bf16(acc[2*n2+1][0],acc[2*n2+1][1],acc[2*n2+1][2],acc[2*n2+1][3],
               a[0],a[1],a[2],a[3], b[2],b[3]);
    }
  }
  int g = lane>>2, tq = lane&3;
  size_t r0 = rowbase + w*16 + g, r1 = r0 + 8;
  #pragma unroll
  for (int nb = 0; nb < 8; nb++){
    int col = nb*8 + tq*2;
    float b0 = qbias[col], b1v = qbias[col+1];
    *(uint32_t*)(qb + r0*64 + col) = pack2((acc[nb][0]+b0)*0.125f, (acc[nb][1]+b1v)*0.125f);
    *(uint32_t*)(qb + r1*64 + col) = pack2((acc[nb][2]+b0)*0.125f, (acc[nb][3]+b1v)*0.125f);
  }
}

// ---------------- sr conv (split-K mma) ----------------
__global__ void __launch_bounds__(256) conv_mma(
    const bf16* __restrict__ h, const bf16* __restrict__ wsr,
    float* __restrict__ part)
{
  __shared__ bf16 Ws[64*72];
  __shared__ bf16 As[128*72];
  int t = threadIdx.x, w = t>>5, lane = t&31;
  int r1 = blockIdx.y;
  int pbase = blockIdx.x * 128;

  float acc[8][4];
  #pragma unroll
  for (int nb = 0; nb < 8; nb++){ acc[nb][0]=acc[nb][1]=acc[nb][2]=acc[nb][3]=0.f; }
  uint32_t As_u = (uint32_t)__cvta_generic_to_shared(As);
  uint32_t Ws_u = (uint32_t)__cvta_generic_to_shared(Ws);
  uint32_t a_base = As_u + ((w*16 + (lane&15))*72 + (lane>>4)*8)*2;
  uint32_t b_off  = (lane&15)*144 + (lane>>4)*16;

  for (int kk = 0; kk < 8; kk++){
    __syncthreads();
    for (int i = t; i < 512; i += 256){
      int row = i>>3, c8 = i&7;
      *(float4*)(Ws + row*72 + c8*8) =
        *(const float4*)(wsr + ((size_t)(r1*512 + kk*64 + row))*64 + c8*8);
    }
    for (int i = t; i < 1024; i += 256){
      int r = i>>3, c8 = i&7;
      int p = pbase + r;
      int b = p>>8, ph = (p>>4)&15, pw = p&15;
      size_t src = ((((size_t)b*128 + ph*8 + r1)*128) + pw*8)*64 + kk*64 + c8*8;
      *(float4*)(As + r*72 + c8*8) = *(const float4*)(h + src);
    }
    __syncthreads();
    #pragma unroll
    for (int kb = 0; kb < 4; kb++){
      uint32_t a[4];
      ldsm_x4(a, a_base + kb*32);
      uint32_t brow = Ws_u + (uint32_t)(kb*16)*144 + b_off;
      #pragma unroll
      for (int n2 = 0; n2 < 4; n2++){
        uint32_t b[4];
        ldsm_x4_t(b, brow + n2*32);
        mma_bf16(acc[2*n2  ][0],acc[2*n2  ][1],acc[2*n2  ][2],acc[2*n2  ][3],
                 a[0],a[1],a[2],a[3], b[0],b[1]);
        mma_bf16(acc[2*n2+1][0],acc[2*n2+1][1],acc[2*n2+1][2],acc[2*n2+1][3],
                 a[0],a[1],a[2],a[3], b[2],b[3]);
      }
    }
  }
  int g = lane>>2, tq = lane&3;
  size_t p0 = pbase + w*16 + g, p1 = p0 + 8;
  #pragma unroll
  for (int nb = 0; nb < 8; nb++){
    int col = nb*8 + tq*2;
    *(float2*)(part + ((size_t)r1*2048 + p0)*64 + col) = make_float2(acc[nb][0], acc[nb][1]);
    *(float2*)(part + ((size_t)r1*2048 + p1)*64 + col) = make_float2(acc[nb][2], acc[nb][3]);
  }
}

// ---------------- reduce conv partials + srn-LN + kv GEMM (64-row tiles) ----------------
__global__ void __launch_bounds__(256) kv_fused(
    const float* __restrict__ part, const float* __restrict__ srb,
    const float* __restrict__ gamma, const float* __restrict__ beta,
    const bf16* __restrict__ wkv, const float* __restrict__ kvbias,
    bf16* __restrict__ kvout)
{
  __shared__ bf16 Ws[64*136];
  __shared__ bf16 As[64*72];
  int t = threadIdx.x, w = t>>5, lane = t&31;
  size_t rowbase = (size_t)blockIdx.x * 64;

  for (int i = t; i < 1024; i += 256){
    int row = i>>4, c8 = i&15;
    *(float4*)(Ws + row*136 + c8*8) = *(const float4*)(wkv + row*128 + c8*8);
  }
  if (t < 128){
    int r = t>>1, half = t&1, col0 = half*32;
    float v[32];
    #pragma unroll
    for (int j = 0; j < 8; j++) *(float4*)(v + j*4) = make_float4(0.f,0.f,0.f,0.f);
    #pragma unroll
    for (int s = 0; s < 8; s++){
      const float* p = part + ((size_t)s*2048 + rowbase + r)*64 + col0;
      #pragma unroll
      for (int j = 0; j < 8; j++){
        float4 q = *(const float4*)(p + j*4);
        v[4*j] += q.x; v[4*j+1] += q.y; v[4*j+2] += q.z; v[4*j+3] += q.w;
      }
    }
    #pragma unroll
    for (int j = 0; j < 8; j++){
      float4 q = *(const float4*)(srb + col0 + j*4);
      v[4*j] += q.x; v[4*j+1] += q.y; v[4*j+2] += q.z; v[4*j+3] += q.w;
    }
    float s = 0.f;
    #pragma unroll
    for (int j = 0; j < 32; j++) s += v[j];
    s += __shfl_xor_sync(0xffffffffu, s, 1);
    float mean = s * (1.0f/64.0f);
    float qv = 0.f;
    #pragma unroll
    for (int j = 0; j < 32; j++){ float d = v[j]-mean; qv += d*d; }
    qv += __shfl_xor_sync(0xffffffffu, qv, 1);
    float rstd = rsqrtf(qv*(1.0f/64.0f) + 1e-5f);
    #pragma unroll
    for (int j = 0; j < 16; j++){
      int c = col0 + 2*j;
      float2 gg = *(const float2*)(gamma + c);
      float2 bb = *(const float2*)(beta + c);
      *(uint32_t*)(As + r*72 + c) = pack2((v[2*j]-mean)*rstd*gg.x + bb.x,
                                          (v[2*j+1]-mean)*rstd*gg.y + bb.y);
    }
  }
  __syncthreads();

  // warp w: rows (w&3)*16.., col half (w>>2)*64..
  float acc[8][4];
  #pragma unroll
  for (int nb = 0; nb < 8; nb++){ acc[nb][0]=acc[nb][1]=acc[nb][2]=acc[nb][3]=0.f; }
  uint32_t As_u = (uint32_t)__cvta_generic_to_shared(As);
  uint32_t Ws_u = (uint32_t)__cvta_generic_to_shared(Ws);
  uint32_t a_base = As_u + (((w&3)*16 + (lane&15))*72 + (lane>>4)*8)*2;
  uint32_t b_off  = (lane&15)*272 + (lane>>4)*16 + (w>>2)*128;
  #pragma unroll
  for (int kb = 0; kb < 4; kb++){
    uint32_t a[4];
    ldsm_x4(a, a_base + kb*32);
    uint32_t brow = Ws_u + (uint32_t)(kb*16)*272 + b_off;
    #pragma unroll
    for (int n2 = 0; n2 < 4; n2++){
      uint32_t b[4];
      ldsm_x4_t(b, brow + n2*32);
      mma_bf16(acc[2*n2  ][0],acc[2*n2  ][1],acc[2*n2  ][2],acc[2*n2  ][3],
               a[0],a[1],a[2],a[3], b[0],b[1]);
      mma_bf16(acc[2*n2+1][0],acc[2*n2+1][1],acc[2*n2+1][2],acc[2*n2+1][3],
               a[0],a[1],a[2],a[3], b[2],b[3]);
    }
  }
  int g = lane>>2, tq = lane&3;
  size_t r0 = rowbase + (w&3)*16 + g, r1 = r0 + 8;
  #pragma unroll
  for (int nb = 0; nb < 8; nb++){
    int col = (w>>2)*64 + nb*8 + tq*2;
    float b0 = kvbias[col], b1 = kvbias[col+1];
    *(uint32_t*)(kvout + r0*128 + col) = pack2(acc[nb][0]+b0, acc[nb][1]+b1);
    *(uint32_t*)(kvout + r1*128 + col) = pack2(acc[nb][2]+b0, acc[nb][3]+b1);
  }
}

// ---- attention (flash, 4 key chunks) + proj + residual + LN2 + fc1 ----
__global__ void __launch_bounds__(256, 2) attn_fused(
    const bf16* __restrict__ q, const bf16* __restrict__ kv,
    const bf16* __restrict__ wp, const float* __restrict__ pbias,
    const float* __restrict__ x, const float* __restrict__ g2,
    const float* __restrict__ b2, const bf16* __restrict__ w1,
    const float* __restrict__ fc1b, float* __restrict__ x2,
    bf16* __restrict__ fbout)
{
  extern __shared__ bf16 sma[];
  bf16* Qs = sma;              // 128 x 72
  bf16* Ks = sma + 128*72;     // 256 x 72 -> later w1 (64 x 264)
  bf16* Vs = Ks  + 256*72;     // 256 x 72
  bf16* Ps = Vs  + 256*72;     // 64 x 72
  int t = threadIdx.x, w = t>>5, lane = t&31;
  int b = blockIdx.y;
  size_t qrow0 = (size_t)b*NTOK + (size_t)blockIdx.x*128;
  const bf16* kvb = kv + (size_t)b*NRTOK*128;

  for (int i = t; i < 1024; i += 256){
    int r = i>>3, c8 = i&7;
    *(float4*)(Qs + r*72 + c8*8) = *(const float4*)(q + (qrow0 + r)*64 + c8*8);
  }
  for (int i = t; i < 2048; i += 256){
    int r = i>>3, c8 = i&7;
    *(float4*)(Ks + r*72 + c8*8) = *(const float4*)(kvb + (size_t)r*128 + c8*8);
  }
  for (int i = t; i < 2048; i += 256){
    int r = i>>3, c8 = i&7;
    *(float4*)(Vs + r*72 + c8*8) = *(const float4*)(kvb + (size_t)r*128 + 64 + c8*8);
  }
  for (int i = t; i < 512; i += 256){
    int r = i>>3, c8 = i&7;
    *(float4*)(Ps + r*72 + c8*8) = *(const float4*)(wp + r*64 + c8*8);
  }
  __syncthreads();

  uint32_t Qs_u = (uint32_t)__cvta_generic_to_shared(Qs);
  uint32_t Ks_u = (uint32_t)__cvta_generic_to_shared(Ks);
  uint32_t Vs_u = (uint32_t)__cvta_generic_to_shared(Vs);
  uint32_t Ps_u = (uint32_t)__cvta_generic_to_shared(Ps);
  uint32_t a_base = Qs_u + ((w*16 + (lane&15))*72 + (lane>>4)*8)*2;
  uint32_t k_off = ((((lane>>4)&1)*8 + (lane&7)))*144 + ((lane>>3)&1)*16;
  uint32_t v_off = (lane&15)*144 + (lane>>4)*16;

  // cache Q fragments (16 regs) — Qs not needed afterwards
  uint32_t af[4][4];
  #pragma unroll
  for (int kb = 0; kb < 4; kb++) ldsm_x4(af[kb], a_base + kb*32);

  float oo[8][4];
  #pragma unroll
  for (int nb = 0; nb < 8; nb++){ oo[nb][0]=oo[nb][1]=oo[nb][2]=oo[nb][3]=0.f; }
  float m0 = -1e30f, m1 = -1e30f, l0 = 0.f, l1 = 0.f;

  #pragma unroll
  for (int c = 0; c < 4; c++){
    float s[8][4];
    #pragma unroll
    for (int nb = 0; nb < 8; nb++){ s[nb][0]=s[nb][1]=s[nb][2]=s[nb][3]=0.f; }
    #pragma unroll
    for (int kb = 0; kb < 4; kb++){
      #pragma unroll
      for (int ng = 0; ng < 4; ng++){
        uint32_t bb[4];
        ldsm_x4(bb, Ks_u + (uint32_t)((c*4 + ng)*16)*144 + kb*32 + k_off);
        mma_bf16(s[2*ng  ][0],s[2*ng  ][1],s[2*ng  ][2],s[2*ng  ][3],
                 af[kb][0],af[kb][1],af[kb][2],af[kb][3], bb[0],bb[1]);
        mma_bf16(s[2*ng+1][0],s[2*ng+1][1],s[2*ng+1][2],s[2*ng+1][3],
                 af[kb][0],af[kb][1],af[kb][2],af[kb][3], bb[2],bb[3]);
      }
    }
    // chunk max (reduce across quad)
    float cm0 = -1e30f, cm1 = -1e30f;
    #pragma unroll
    for (int nb = 0; nb < 8; nb++){
      cm0 = fmaxf(cm0, fmaxf(s[nb][0], s[nb][1]));
      cm1 = fmaxf(cm1, fmaxf(s[nb][2], s[nb][3]));
    }
    cm0 = fmaxf(cm0, __shfl_xor_sync(0xffffffffu, cm0, 1));
    cm0 = fmaxf(cm0, __shfl_xor_sync(0xffffffffu, cm0, 2));
    cm1 = fmaxf(cm1, __shfl_xor_sync(0xffffffffu, cm1, 1));
    cm1 = fmaxf(cm1, __shfl_xor_sync(0xffffffffu, cm1, 2));
    float nm0 = fmaxf(m0, cm0), nm1 = fmaxf(m1, cm1);
    float sc0 = __expf(m0 - nm0), sc1 = __expf(m1 - nm1);
    m0 = nm0; m1 = nm1;
    float cs0 = 0.f, cs1 = 0.f;
    #pragma unroll
    for (int nb = 0; nb < 8; nb++){
      s[nb][0] = __expf(s[nb][0] - m0); cs0 += s[nb][0];
      s[nb][1] = __expf(s[nb][1] - m0); cs0 += s[nb][1];
      s[nb][2] = __expf(s[nb][2] - m1); cs1 += s[nb][2];
      s[nb][3] = __expf(s[nb][3] - m1); cs1 += s[nb][3];
    }
    l0 = l0*sc0 + cs0;
    l1 = l1*sc1 + cs1;
    #pragma unroll
    for (int nb = 0; nb < 8; nb++){
      oo[nb][0] *= sc0; oo[nb][1] *= sc0; oo[nb][2] *= sc1; oo[nb][3] *= sc1;
    }
    // PV for this chunk
    #pragma unroll
    for (int j = 0; j < 2; j++){
      uint32_t a0 = pack2(s[4*j  ][0], s[4*j  ][1]);
      uint32_t a1 = pack2(s[4*j  ][2], s[4*j  ][3]);
      uint32_t a2 = pack2(s[4*j+1][0], s[4*j+1][1]);
      uint32_t a3 = pack2(s[4*j+1][2], s[4*j+1][3]);
      uint32_t c0 = pack2(s[4*j+2][0], s[4*j+2][1]);
      uint32_t c1 = pack2(s[4*j+2][2], s[4*j+2][3]);
      uint32_t c2 = pack2(s[4*j+3][0], s[4*j+3][1]);
      uint32_t c3 = pack2(s[4*j+3][2], s[4*j+3][3]);
      uint32_t base0 = Vs_u + (uint32_t)(c*64 + j*32)*144 + v_off;
      uint32_t base1 = base0 + 16*144;
      #pragma unroll
      for (int n2 = 0; n2 < 4; n2++){
        uint32_t bb[4];
        ldsm_x4_t(bb, base0 + n2*32);
        mma_bf16(oo[2*n2  ][0],oo[2*n2  ][1],oo[2*n2  ][2],oo[2*n2  ][3],
                 a0,a1,a2,a3, bb[0],bb[1]);
        mma_bf16(oo[2*n2+1][0],oo[2*n2+1][1],oo[2*n2+1][2],oo[2*n2+1][3],
                 a0,a1,a2,a3, bb[2],bb[3]);
        ldsm_x4_t(bb, base1 + n2*32);
        mma_bf16(oo[2*n2  ][0],oo[2*n2  ][1],oo[2*n2  ][2],oo[2*n2  ][3],
                 c0,c1,c2,c3, bb[0],bb[1]);
        mma_bf16(oo[2*n2+1][0],oo[2*n2+1][1],oo[2*n2+1][2],oo[2*n2+1][3],
                 c0,c1,c2,c3, bb[2],bb[3]);
      }
    }
  }

  // final normalization (l reduced across quad here)
  l0 += __shfl_xor_sync(0xffffffffu, l0, 1);
  l0 += __shfl_xor_sync(0xffffffffu, l0, 2);
  l1 += __shfl_xor_sync(0xffffffffu, l1, 1);
  l1 += __shfl_xor_sync(0xffffffffu, l1, 2);
  float inv0 = __frcp_rn(l0), inv1 = __frcp_rn(l1);
  #pragma unroll
  for (int nb = 0; nb < 8; nb++){
    oo[nb][0] *= inv0; oo[nb][1] *= inv0; oo[nb][2] *= inv1; oo[nb][3] *= inv1;
  }

  // Ks dead now: async-load w1 (64x256 -> stride 264) into its space
  __syncthreads();
  for (int i = t; i < 2048; i += 256){
    int row = i>>5, c8 = i&31;
    cp_async16(Ks_u + (uint32_t)(row*264 + c8*8)*2, w1 + (size_t)row*256 + c8*8);
  }
  cp_async_commit();

  // proj GEMM
  float acc2[8][4];
  #pragma unroll
  for (int nb = 0; nb < 8; nb++){ acc2[nb][0]=acc2[nb][1]=acc2[nb][2]=acc2[nb][3]=0.f; }
  #pragma unroll
  for (int kb = 0; kb < 4; kb++){
    uint32_t a0 = pack2(oo[2*kb  ][0], oo[2*kb  ][1]);
    uint32_t a1 = pack2(oo[2*kb  ][2], oo[2*kb  ][3]);
    uint32_t a2 = pack2(oo[2*kb+1][0], oo[2*kb+1][1]);
    uint32_t a3 = pack2(oo[2*kb+1][2], oo[2*kb+1][3]);
    uint32_t brow = Ps_u + (uint32_t)kb*16*144 + v_off;
    #pragma unroll
    for (int n2 = 0; n2 < 4; n2++){
      uint32_t bb[4];
      ldsm_x4_t(bb, brow + n2*32);
      mma_bf16(acc2[2*n2  ][0],acc2[2*n2  ][1],acc2[2*n2  ][2],acc2[2*n2  ][3],
               a0,a1,a2,a3, bb[0],bb[1]);
      mma_bf16(acc2[2*n2+1][0],acc2[2*n2+1][1],acc2[2*n2+1][2],acc2[2*n2+1][3],
               a0,a1,a2,a3, bb[2],bb[3]);
    }
  }

  // epilogue: x2 = x + proj; hn = LN2(x2)
  int g = lane>>2, tq = lane&3;
  size_t r0 = qrow0 + w*16 + g, r1 = r0 + 8;
  float v0[16], v1[16];
  float s0 = 0.f, s1 = 0.f;
  #pragma unroll
  for (int nb = 0; nb < 8; nb++){
    int col = nb*8 + tq*2;
    float pb0 = pbias[col], pb1 = pbias[col+1];
    float2 xx0 = *(const float2*)(x + r0*64 + col);
    float2 xx1 = *(const float2*)(x + r1*64 + col);
    v0[2*nb]   = acc2[nb][0] + pb0 + xx0.x;
    v0[2*nb+1] = acc2[nb][1] + pb1 + xx0.y;
    v1[2*nb]   = acc2[nb][2] + pb0 + xx1.x;
    v1[2*nb+1] = acc2[nb][3] + pb1 + xx1.y;
    s0 += v0[2*nb] + v0[2*nb+1];
    s1 += v1[2*nb] + v1[2*nb+1];
  }
  s0 += __shfl_xor_sync(0xffffffffu, s0, 1);
  s0 += __shfl_xor_sync(0xffffffffu, s0, 2);
  s1 += __shfl_xor_sync(0xffffffffu, s1, 1);
  s1 += __shfl_xor_sync(0xffffffffu, s1, 2);
  float m0e = s0*(1.0f/64.0f), m1e = s1*(1.0f/64.0f);
  float q0 = 0.f, q1 = 0.f;
  #pragma unroll
  for (int j = 0; j < 16; j++){
    float d0 = v0[j]-m0e, d1 = v1[j]-m1e;
    q0 += d0*d0; q1 += d1*d1;
  }
  q0 += __shfl_xor_sync(0xffffffffu, q0, 1);
  q0 += __shfl_xor_sync(0xffffffffu, q0, 2);
  q1 += __shfl_xor_sync(0xffffffffu, q1, 1);
  q1 += __shfl_xor_sync(0xffffffffu, q1, 2);
  float rs0 = rsqrtf(q0*(1.0f/64.0f) + 1e-5f);
  float rs1 = rsqrtf(q1*(1.0f/64.0f) + 1e-5f);

  float hn0[16], hn1[16];
  #pragma unroll
  for (int nb = 0; nb < 8; nb++){
    int col = nb*8 + tq*2;
    *(float2*)(x2 + r0*64 + col) = make_float2(v0[2*nb], v0[2*nb+1]);
    *(float2*)(x2 + r1*64 + col) = make_float2(v1[2*nb], v1[2*nb+1]);
    float2 gg = *(const float2*)(g2 + col);
    float2 bb = *(const float2*)(b2 + col);
    hn0[2*nb]   = (v0[2*nb]  -m0e)*rs0*gg.x + bb.x;
    hn0[2*nb+1] = (v0[2*nb+1]-m0e)*rs0*gg.y + bb.y;
    hn1[2*nb]   = (v1[2*nb]  -m1e)*rs1*gg.x + bb.x;
    hn1[2*nb+1] = (v1[2*nb+1]-m1e)*rs1*gg.y + bb.y;
  }

  // fc1: f = hn @ w1 + fc1b (two 128-col halves)
  cp_async_wait0();
  __syncthreads();
  uint32_t b_off1 = (lane&15)*528 + (lane>>4)*16;
  #pragma unroll
  for (int h = 0; h < 2; h++){
    float fa[16][4];
    #pragma unroll
    for (int nb = 0; nb < 16; nb++){ fa[nb][0]=fa[nb][1]=fa[nb][2]=fa[nb][3]=0.f; }
    #pragma unroll
    for (int kb = 0; kb < 4; kb++){
      uint32_t a0 = pack2(hn0[4*kb],   hn0[4*kb+1]);
      uint32_t a1 = pack2(hn1[4*kb],   hn1[4*kb+1]);
      uint32_t a2 = pack2(hn0[4*kb+2], hn0[4*kb+3]);
      uint32_t a3 = pack2(hn1[4*kb+2], hn1[4*kb+3]);
      uint32_t brow = Ks_u + (uint32_t)(kb*16)*528 + h*256 + b_off1;
      #pragma unroll
      for (int n2 = 0; n2 < 8; n2++){
        uint32_t bb[4];
        ldsm_x4_t(bb, brow + n2*32);
        mma_bf16(fa[2*n2  ][0],fa[2*n2  ][1],fa[2*n2  ][2],fa[2*n2  ][3],
                 a0,a1,a2,a3, bb[0],bb[1]);
        mma_bf16(fa[2*n2+1][0],fa[2*n2+1][1],fa[2*n2+1][2],fa[2*n2+1][3],
                 a0,a1,a2,a3, bb[2],bb[3]);
      }
    }
    #pragma unroll
    for (int nb = 0; nb < 16; nb++){
      int col = h*128 + nb*8 + tq*2;
      float b0 = fc1b[col], b1 = fc1b[col+1];
      *(uint32_t*)(fbout + r0*256 + col) = pack2(fa[nb][0]+b0, fa[nb][1]+b1);
      *(uint32_t*)(fbout + r1*256 + col) = pack2(fa[nb][2]+b0, fa[nb][3]+b1);
    }
  }
}

// ---------------- fused dwconv3x3 + GELU + fc2 + residual ----------------
__global__ void __launch_bounds__(256) fc2_fused(
    const bf16* __restrict__ f, const float* __restrict__ dw,
    const bf16* __restrict__ w2, const float* __restrict__ bias2,
    const float* __restrict__ x2, float* __restrict__ out)
{
  extern __shared__ bf16 smf[];
  bf16* Ws = smf;                 // 256 x 72
  bf16* Fs = smf + 256*72;        // 3 x 128 x 72
  bf16* Gs = Fs  + 3*128*72;      // 128 x 72
  int t = threadIdx.x, w = t>>5, lane = t&31;
  int by = blockIdx.x;
  int b = by >> 7, y = by & 127;
  size_t tokbase = (size_t)b*NTOK + (size_t)y*128;

  for (int i = t; i < 2048; i += 256){
    int row = i>>3, c8 = i&7;
    *(float4*)(Ws + row*72 + c8*8) = *(const float4*)(w2 + row*64 + c8*8);
  }

  float acc[8][4];
  #pragma unroll
  for (int nb = 0; nb < 8; nb++){ acc[nb][0]=acc[nb][1]=acc[nb][2]=acc[nb][3]=0.f; }
  uint32_t Ws_u = (uint32_t)__cvta_generic_to_shared(Ws);
  uint32_t Gs_u = (uint32_t)__cvta_generic_to_shared(Gs);
  uint32_t a_base = Gs_u + ((w*16 + (lane&15))*72 + (lane>>4)*8)*2;
  uint32_t b_off  = (lane&15)*144 + (lane>>4)*16;

  int chl = lane*2;
  int px0 = w*16;

  for (int kc = 0; kc < 256; kc += 64){
    __syncthreads();
    for (int i = t; i < 3072; i += 256){
      int row3 = i>>10, rem = i&1023, px = rem>>3, c8 = rem&7;
      int yy = y + row3 - 1;
      float4 val;
      if (yy >= 0 && yy < 128)
        val = *(const float4*)(f + ((size_t)b*NTOK + (size_t)yy*128 + px)*256 + kc + c8*8);
      else
        val = make_float4(0.f,0.f,0.f,0.f);
      *(float4*)(Fs + row3*9216 + px*72 + c8*8) = val;
    }
    __syncthreads();
    {
      float w9[2][9];
      #pragma unroll
      for (int i = 0; i < 9; i++){
        float2 wv = *(const float2*)(dw + i*256 + kc + chl);
        w9[0][i] = wv.x; w9[1][i] = wv.y;
      }
      uint32_t colv[3][3];
      #pragma unroll
      for (int dy = 0; dy < 3; dy++){
        colv[0][dy] = (px0 > 0) ? *(uint32_t*)(Fs + dy*9216 + (px0-1)*72 + chl) : 0u;
        colv[1][dy] = *(uint32_t*)(Fs + dy*9216 + px0*72 + chl);
      }
      #pragma unroll
      for (int pi = 0; pi < 16; pi++){
        int px = px0 + pi;
        #pragma unroll
        for (int dy = 0; dy < 3; dy++)
          colv[2][dy] = (px+1 < 128) ? *(uint32_t*)(Fs + dy*9216 + (px+1)*72 + chl) : 0u;
        float a0 = 0.f, a1 = 0.f;
        #pragma unroll
        for (int dy = 0; dy < 3; dy++)
          #pragma unroll
          for (int dx = 0; dx < 3; dx++){
            float2 vv = __bfloat1622float2(
                *reinterpret_cast<const __nv_bfloat162*>(&colv[dx][dy]));
            a0 = fmaf(vv.x, w9[0][dy*3+dx], a0);
            a1 = fmaf(vv.y, w9[1][dy*3+dx], a1);
          }
        a0 = 0.5f*a0*(1.0f + erff(a0*0.70710678118654752f));
        a1 = 0.5f*a1*(1.0f + erff(a1*0.70710678118654752f));
        *(uint32_t*)(Gs + px*72 + chl) = pack2(a0, a1);
        #pragma unroll
        for (int dy = 0; dy < 3; dy++){ colv[0][dy] = colv[1][dy]; colv[1][dy] = colv[2][dy]; }
      }
    }
    __syncwarp();
    #pragma unroll
    for (int kb = 0; kb < 4; kb++){
      uint32_t a[4];
      ldsm_x4(a, a_base + kb*32);
      uint32_t brow = Ws_u + (uint32_t)(kc + kb*16)*144 + b_off;
      #pragma unroll
      for (int n2 = 0; n2 < 4; n2++){
        uint32_t bb[4];
        ldsm_x4_t(bb, brow + n2*32);
        mma_bf16(acc[2*n2  ][0],acc[2*n2  ][1],acc[2*n2  ][2],acc[2*n2  ][3],
                 a[0],a[1],a[2],a[3], bb[0],bb[1]);
        mma_bf16(acc[2*n2+1][0],acc[2*n2+1][1],acc[2*n2+1][2],acc[2*n2+1][3],
                 a[0],a[1],a[2],a[3], bb[2],bb[3]);
      }
    }
  }

  int g = lane>>2, tq = lane&3;
  size_t r0 = tokbase + w*16 + g, r1 = r0 + 8;
  #pragma unroll
  for (int nb = 0; nb < 8; nb++){
    int col = nb*8 + tq*2;
    float b0 = bias2[col], b1 = bias2[col+1];
    float2 q0 = *(const float2*)(x2 + r0*64 + col);
    float2 q1 = *(const float2*)(x2 + r1*64 + col);
    *(float2*)(out + r0*64 + col) = make_float2(acc[nb][0]+b0+q0.x, acc[nb][1]+b1+q0.y);
    *(float2*)(out + r1*64 + col) = make_float2(acc[nb][2]+b0+q1.x, acc[nb][3]+b1+q1.y);
  }
}

// ---------------- launch ----------------
extern "C" void kernel_launch(void* const* d_in, const int* in_sizes, int n_in,
                              void* d_out, int out_size)
{
  const float* x      = (const float*)d_in[0];
  const float* ln1_g  = (const float*)d_in[3];
  const float* ln1_b  = (const float*)d_in[4];
  const float* q_w    = (const float*)d_in[5];
  const float* q_b    = (const float*)d_in[6];
  const float* kv_w   = (const float*)d_in[7];
  const float* kv_b   = (const float*)d_in[8];
  const float* proj_w = (const float*)d_in[9];
  const float* proj_b = (const float*)d_in[10];
  const float* sr_w   = (const float*)d_in[11];
  const float* sr_b   = (const float*)d_in[12];
  const float* srn_g  = (const float*)d_in[13];
  const float* srn_b  = (const float*)d_in[14];
  const float* ln2_g  = (const float*)d_in[15];
  const float* ln2_b  = (const float*)d_in[16];
  const float* fc1_w  = (const float*)d_in[17];
  const float* fc1_b  = (const float*)d_in[18];
  const float* dw_w   = (const float*)d_in[19];
  const float* fc2_w  = (const float*)d_in[20];
  const float* fc2_b  = (const float*)d_in[21];
  float* out = (float*)d_out;

  bf16 *hb,*qb,*fb,*kvbuf,*wq,*wkv,*wp,*wsr,*w1,*w2;
  float *x2,*convp;
  cudaGetSymbolAddress((void**)&hb,  g_hb);
  cudaGetSymbolAddress((void**)&qb,  g_qb);
  cudaGetSymbolAddress((void**)&x2,  g_x2);
  cudaGetSymbolAddress((void**)&fb,  g_fb);
  cudaGetSymbolAddress((void**)&convp, g_convp);
  cudaGetSymbolAddress((void**)&kvbuf, g_kvb);
  cudaGetSymbolAddress((void**)&wq,  g_wq);
  cudaGetSymbolAddress((void**)&wkv, g_wkv);
  cudaGetSymbolAddress((void**)&wp,  g_wp);
  cudaGetSymbolAddress((void**)&wsr, g_wsr);
  cudaGetSymbolAddress((void**)&w1,  g_w1);
  cudaGetSymbolAddress((void**)&w2,  g_w2);

  const int SM_ATTN = (128 + 256 + 256 + 64)*72*2;    // 101376
  const int SM_FC2  = (256 + 3*128 + 128)*72*2;       // 110592

  cudaFuncSetAttribute((const void*)attn_fused,
                       cudaFuncAttributeMaxDynamicSharedMemorySize, SM_ATTN);
  cudaFuncSetAttribute((const void*)fc2_fused,
                       cudaFuncAttributeMaxDynamicSharedMemorySize, SM_FC2);

  CvtArgs ca = { q_w, kv_w, proj_w, sr_w, fc1_w, fc2_w, wq, wkv, wp, wsr, w1, w2 };
  cvt_all<<<1216, 256>>>(ca);
  ln1q_kernel<<<1024, 256>>>(x, wq, q_b, ln1_g, ln1_b, hb, qb);
  conv_mma<<<dim3(16,8), 256>>>(hb, wsr, convp);
  kv_fused<<<32, 256>>>(convp, sr_b, srn_g, srn_b, wkv, kv_b, kvbuf);
  attn_fused<<<dim3(128, BB), 256, SM_ATTN>>>(qb, kvbuf, wp, proj_b, x,
                                              ln2_g, ln2_b, w1, fc1_b, x2, fb);
  fc2_fused<<<1024, 256, SM_FC2>>>(fb, dw_w, w2, fc2_b, x2, out);
}